// round 4
// baseline (speedup 1.0000x reference)
#include <cuda_runtime.h>
#include <cstdint>
#include <math.h>

constexpr int IMH = 256, IMW = 256;
constexpr int HWSZ = IMH * IMW;       // 65536
constexpr int BB = 2;

// ---------------- scratch (device globals; no runtime allocation) ----------------
__device__ float g_qkin  [(size_t)BB * 100 * HWSZ];
__device__ float g_qureys[(size_t)BB *  96 * HWSZ];
__device__ float g_value [(size_t)BB *  96 * HWSZ];
__device__ float g_val   [(size_t)BB *  96 * HWSZ];
__device__ float g_off   [(size_t)BB *  96 * HWSZ];
__device__ float g_aw    [(size_t)BB *  48 * HWSZ];
__device__ float g_attn  [(size_t)BB *  32 * HWSZ];
__device__ float g_out1  [(size_t)BB *  32 * HWSZ];
__device__ float g_out2  [(size_t)BB *  32 * HWSZ];
__device__ float g_tseq  [(size_t)BB *  64 * HWSZ];
__device__ float g_ff1   [(size_t)BB *  32 * HWSZ];
__device__ float g_out3  [(size_t)BB *  32 * HWSZ];

__device__ __forceinline__ float lrelu(float v) { return v >= 0.f ? v : 0.1f * v; }

// ---------------- packed f32x2 helpers (Blackwell FFMA2) ----------------
__device__ __forceinline__ void ffma2(unsigned long long& acc, unsigned long long x,
                                      unsigned long long w)
{
    asm("fma.rn.f32x2 %0, %1, %2, %0;" : "+l"(acc) : "l"(x), "l"(w));
}
__device__ __forceinline__ unsigned long long packf2(float lo, float hi)
{
    unsigned long long r;
    asm("mov.b64 %0, {%1, %2};" : "=l"(r) : "f"(lo), "f"(hi));
    return r;
}
__device__ __forceinline__ void unpackf2(unsigned long long v, float& lo, float& hi)
{
    asm("mov.b64 {%0, %1}, %2;" : "=f"(lo), "=f"(hi) : "l"(v));
}

// ---------------- kernel 1: build qk_in (flow warps + concat) ----------------
__device__ __forceinline__ void sample32(const float* __restrict__ img, float sx, float sy,
                                         float* __restrict__ dst, int q)
{
    float x0f = floorf(sx), y0f = floorf(sy);
    float lx = sx - x0f, ly = sy - y0f;
    int x0 = (int)x0f, y0 = (int)y0f;
    float w00 = (1.f - lx) * (1.f - ly);
    float w01 = lx * (1.f - ly);
    float w10 = (1.f - lx) * ly;
    float w11 = lx * ly;
    bool vx0 = (unsigned)x0       < (unsigned)IMW;
    bool vx1 = (unsigned)(x0 + 1) < (unsigned)IMW;
    bool vy0 = (unsigned)y0       < (unsigned)IMH;
    bool vy1 = (unsigned)(y0 + 1) < (unsigned)IMH;
    int cx0 = min(max(x0, 0), IMW - 1), cx1 = min(max(x0 + 1, 0), IMW - 1);
    int cy0 = min(max(y0, 0), IMH - 1), cy1 = min(max(y0 + 1, 0), IMH - 1);
    int i00 = cy0 * IMW + cx0, i01 = cy0 * IMW + cx1;
    int i10 = cy1 * IMW + cx0, i11 = cy1 * IMW + cx1;
    float m00 = (vx0 && vy0) ? w00 : 0.f;
    float m01 = (vx1 && vy0) ? w01 : 0.f;
    float m10 = (vx0 && vy1) ? w10 : 0.f;
    float m11 = (vx1 && vy1) ? w11 : 0.f;
    #pragma unroll 4
    for (int c = 0; c < 32; ++c) {
        const float* p = img + (size_t)c * HWSZ;
        dst[(size_t)c * HWSZ + q] = m00 * p[i00] + m01 * p[i01] + m10 * p[i10] + m11 * p[i11];
    }
}

__global__ void build_qkin_kernel(const float* __restrict__ frame,
                                  const float* __restrict__ flow_f,
                                  const float* __restrict__ flow_b,
                                  float* __restrict__ qkin)
{
    int id = blockIdx.x * blockDim.x + threadIdx.x;
    if (id >= BB * HWSZ) return;
    int b = id / HWSZ, q = id % HWSZ;
    int px = q & (IMW - 1), py = q >> 8;

    const float* fb = flow_b + (size_t)b * 2 * 2 * HWSZ;
    float fbx = fb[q], fby = fb[HWSZ + q];
    const float* ff = flow_f + (size_t)b * 2 * 2 * HWSZ + (size_t)2 * HWSZ;
    float ffx = ff[q], ffy = ff[HWSZ + q];

    float* dst = qkin + (size_t)b * 100 * HWSZ;
    sample32(frame + ((size_t)b * 3 + 0) * 32 * HWSZ, (float)px + fbx, (float)py + fby, dst, q);
    const float* f1 = frame + ((size_t)b * 3 + 1) * 32 * HWSZ;
    #pragma unroll 4
    for (int c = 0; c < 32; ++c)
        dst[(size_t)(32 + c) * HWSZ + q] = f1[(size_t)c * HWSZ + q];
    sample32(frame + ((size_t)b * 3 + 2) * 32 * HWSZ, (float)px + ffx, (float)py + ffy,
             dst + (size_t)64 * HWSZ, q);
    dst[(size_t)96 * HWSZ + q] = ffx;
    dst[(size_t)97 * HWSZ + q] = ffy;
    dst[(size_t)98 * HWSZ + q] = fbx;
    dst[(size_t)99 * HWSZ + q] = fby;
}

// ---------------- cp.async helpers ----------------
__device__ __forceinline__ void cpasync4(unsigned int dst, const float* src, bool ok)
{
    int sz = ok ? 4 : 0;
    asm volatile("cp.async.ca.shared.global [%0], [%1], 4, %2;\n"
                 :: "r"(dst), "l"(src), "r"(sz));
}
__device__ __forceinline__ void cpasync_commit() {
    asm volatile("cp.async.commit_group;\n" ::: "memory");
}
__device__ __forceinline__ void cpasync_wait0() {
    asm volatile("cp.async.wait_group 0;\n" ::: "memory");
}

// ---------------- pipelined tiled 3x3 conv, packed-FFMA2 mainloop ----------------
// tile: 32(x) x 16(y) output pixels, 16 out channels per block,
// each thread: 2 pixels (rows py, py+8) x 16 oc, acc as f32x2 pairs.
// Weights duplicated (w,w) in smem so LDS.128 yields two broadcast pairs.
template<int CIN, int DIL, int ACT, bool RES>
__global__ void __launch_bounds__(256, 3) conv3x3_pipe(
    const float* __restrict__ in, const float* __restrict__ Wt,
    const float* __restrict__ bias, const float* __restrict__ res, size_t resStride,
    float* __restrict__ out, int COUT)
{
    constexpr int TX = 32, TY = 16, OCB = 16;
    constexpr int IW = TX + 2 * DIL, IH = TY + 2 * DIL;
    constexpr int NCH = CIN / 4;
    constexpr int TILE_ELEMS = 4 * IH * IW;
    __shared__ float s_in[2][4][IH][IW];
    __shared__ __align__(16) float2 s_w[2][4][9][OCB];   // (w,w) duplicated

    const int tid = threadIdx.x;
    const int px = tid & 31, py = tid >> 5;          // px 0..31, py 0..7
    const int x0 = blockIdx.x * TX, y0 = blockIdx.y * TY;
    const int ngrp = COUT >> 4;
    const int img = blockIdx.z / ngrp;
    const int ocBase = (blockIdx.z % ngrp) * OCB;
    const float* inImg = in + (size_t)img * CIN * HWSZ;

    unsigned long long accP[OCB];
    #pragma unroll
    for (int i = 0; i < OCB; ++i) accP[i] = 0ULL;

    // ---- prologue: chunk 0 into buffer 0 ----
    {
        #pragma unroll 4
        for (int idx = tid; idx < TILE_ELEMS; idx += 256) {
            int ci = idx / (IH * IW);
            int rem = idx % (IH * IW);
            int ly = rem / IW, lx = rem % IW;
            int gy = y0 - DIL + ly, gx = x0 - DIL + lx;
            bool ok = ((unsigned)gy < (unsigned)IMH) && ((unsigned)gx < (unsigned)IMW);
            int cgy = ok ? gy : 0, cgx = ok ? gx : 0;
            const float* src = inImg + (size_t)ci * HWSZ + cgy * IMW + cgx;
            unsigned int dst = (unsigned int)__cvta_generic_to_shared(&s_in[0][ci][ly][lx]);
            cpasync4(dst, src, ok);
        }
        cpasync_commit();
        #pragma unroll 3
        for (int idx = tid; idx < 4 * 9 * OCB; idx += 256) {
            int oc = idx & 15;
            int k  = (idx >> 4) % 9;
            int ci = (idx >> 4) / 9;
            float w = Wt[((size_t)(ocBase + oc) * CIN + ci) * 9 + k];
            s_w[0][ci][k][oc] = make_float2(w, w);
        }
        cpasync_wait0();
        __syncthreads();
    }

    int buf = 0;
    #pragma unroll 1
    for (int cc = 0; cc < NCH; ++cc) {
        // ---- prefetch next chunk into buf^1 ----
        if (cc + 1 < NCH) {
            const int nb = buf ^ 1;
            const int ciBase = (cc + 1) * 4;
            #pragma unroll 4
            for (int idx = tid; idx < TILE_ELEMS; idx += 256) {
                int ci = idx / (IH * IW);
                int rem = idx % (IH * IW);
                int ly = rem / IW, lx = rem % IW;
                int gy = y0 - DIL + ly, gx = x0 - DIL + lx;
                bool ok = ((unsigned)gy < (unsigned)IMH) && ((unsigned)gx < (unsigned)IMW);
                int cgy = ok ? gy : 0, cgx = ok ? gx : 0;
                const float* src = inImg + (size_t)(ciBase + ci) * HWSZ + cgy * IMW + cgx;
                unsigned int dst = (unsigned int)__cvta_generic_to_shared(&s_in[nb][ci][ly][lx]);
                cpasync4(dst, src, ok);
            }
            #pragma unroll 3
            for (int idx = tid; idx < 4 * 9 * OCB; idx += 256) {
                int oc = idx & 15;
                int k  = (idx >> 4) % 9;
                int ci = (idx >> 4) / 9;
                float w = Wt[((size_t)(ocBase + oc) * CIN + ciBase + ci) * 9 + k];
                s_w[nb][ci][k][oc] = make_float2(w, w);
            }
        }
        cpasync_commit();

        // ---- compute current chunk (packed FFMA2) ----
        #pragma unroll
        for (int ci = 0; ci < 4; ++ci) {
            #pragma unroll
            for (int k = 0; k < 9; ++k) {
                const int ky = k / 3, kx = k % 3;
                float xa = s_in[buf][ci][py +     ky * DIL][px + kx * DIL];
                float xb = s_in[buf][ci][py + 8 + ky * DIL][px + kx * DIL];
                unsigned long long xp = packf2(xa, xb);
                const ulonglong2* wp = reinterpret_cast<const ulonglong2*>(&s_w[buf][ci][k][0]);
                #pragma unroll
                for (int o2 = 0; o2 < 8; ++o2) {
                    ulonglong2 w2 = wp[o2];
                    ffma2(accP[o2 * 2 + 0], xp, w2.x);
                    ffma2(accP[o2 * 2 + 1], xp, w2.y);
                }
            }
        }

        cpasync_wait0();
        __syncthreads();
        buf ^= 1;
    }

    const int ox = x0 + px;
    const int oyA = y0 + py, oyB = y0 + py + 8;
    const size_t outImg = (size_t)img * COUT * HWSZ;
    #pragma unroll
    for (int oc = 0; oc < OCB; ++oc) {
        float vA, vB;
        unpackf2(accP[oc], vA, vB);
        float bv = bias[ocBase + oc];
        vA += bv;
        vB += bv;
        if (RES) {
            const float* rp = res + (size_t)img * resStride + (size_t)(ocBase + oc) * HWSZ;
            vA += rp[oyA * IMW + ox];
            vB += rp[oyB * IMW + ox];
        }
        if (ACT) { vA = lrelu(vA); vB = lrelu(vB); }
        size_t chOff = outImg + (size_t)(ocBase + oc) * HWSZ;
        out[chOff + oyA * IMW + ox] = vA;
        out[chOff + oyB * IMW + ox] = vB;
    }
}

// ---------------- deformable attention ----------------
__global__ void deform_attn_kernel(const float* __restrict__ val,
                                   const float* __restrict__ off,
                                   const float* __restrict__ awl,
                                   float* __restrict__ out)
{
    int id = blockIdx.x * blockDim.x + threadIdx.x;
    if (id >= BB * 4 * HWSZ) return;
    int q = id % HWSZ;
    int head = (id / HWSZ) & 3;
    int b = id / (4 * HWSZ);
    int px = q & (IMW - 1), py = q >> 8;

    const float* awp = awl + ((size_t)b * 48 + head * 12) * HWSZ + q;
    float lg[12];
    float mx = -1e30f;
    #pragma unroll
    for (int i = 0; i < 12; ++i) { lg[i] = awp[(size_t)i * HWSZ]; mx = fmaxf(mx, lg[i]); }
    float s = 0.f;
    #pragma unroll
    for (int i = 0; i < 12; ++i) { lg[i] = expf(lg[i] - mx); s += lg[i]; }
    float inv = 1.f / s;

    float acc[8];
    #pragma unroll
    for (int e = 0; e < 8; ++e) acc[e] = 0.f;

    const float* offp = off + ((size_t)b * 96 + head * 24) * HWSZ + q;

    for (int l = 0; l < 3; ++l) {
        const float* vbase = val + (((size_t)b * 3 + l) * 32 + head * 8) * HWSZ;
        #pragma unroll
        for (int p = 0; p < 4; ++p) {
            int ch = (l * 4 + p) * 2;
            float sx = (float)px + offp[(size_t)ch * HWSZ];
            float sy = (float)py + offp[(size_t)(ch + 1) * HWSZ];
            float a = lg[l * 4 + p] * inv;

            float x0f = floorf(sx), y0f = floorf(sy);
            float lx = sx - x0f, ly = sy - y0f;
            int x0 = (int)x0f, y0 = (int)y0f;
            float w00 = (1.f - lx) * (1.f - ly);
            float w01 = lx * (1.f - ly);
            float w10 = (1.f - lx) * ly;
            float w11 = lx * ly;
            bool vx0 = (unsigned)x0       < (unsigned)IMW;
            bool vx1 = (unsigned)(x0 + 1) < (unsigned)IMW;
            bool vy0 = (unsigned)y0       < (unsigned)IMH;
            bool vy1 = (unsigned)(y0 + 1) < (unsigned)IMH;
            int cx0 = min(max(x0, 0), IMW - 1), cx1 = min(max(x0 + 1, 0), IMW - 1);
            int cy0 = min(max(y0, 0), IMH - 1), cy1 = min(max(y0 + 1, 0), IMH - 1);
            float c00 = (vx0 && vy0) ? a * w00 : 0.f;
            float c01 = (vx1 && vy0) ? a * w01 : 0.f;
            float c10 = (vx0 && vy1) ? a * w10 : 0.f;
            float c11 = (vx1 && vy1) ? a * w11 : 0.f;
            int i00 = cy0 * IMW + cx0, i01 = cy0 * IMW + cx1;
            int i10 = cy1 * IMW + cx0, i11 = cy1 * IMW + cx1;
            #pragma unroll
            for (int e = 0; e < 8; ++e) {
                const float* vp = vbase + (size_t)e * HWSZ;
                acc[e] += c00 * vp[i00] + c01 * vp[i01] + c10 * vp[i10] + c11 * vp[i11];
            }
        }
    }

    float* op = out + ((size_t)b * 32 + head * 8) * HWSZ + q;
    #pragma unroll
    for (int e = 0; e < 8; ++e) op[(size_t)e * HWSZ] = acc[e];
}

// ---------------- concat [out2, srcframe[:,1]] ----------------
__global__ void build_tseq_kernel(const float* __restrict__ out2,
                                  const float* __restrict__ srcframe,
                                  float* __restrict__ tseq)
{
    int id = blockIdx.x * blockDim.x + threadIdx.x;
    if (id >= BB * 64 * HWSZ) return;
    int q = id % HWSZ;
    int c = (id / HWSZ) & 63;
    int b = id / (64 * HWSZ);
    float v;
    if (c < 32) v = out2[((size_t)b * 32 + c) * HWSZ + q];
    else        v = srcframe[(((size_t)b * 3 + 1) * 32 + (c - 32)) * HWSZ + q];
    tseq[((size_t)b * 64 + c) * HWSZ + q] = v;
}

// ---------------- final 1x1 conv + lrelu ----------------
__global__ void conv1x1_lrelu_kernel(const float* __restrict__ in,
                                     const float* __restrict__ Wt,
                                     const float* __restrict__ bias,
                                     float* __restrict__ out)
{
    __shared__ float s_w[32][32];
    __shared__ float s_b[32];
    int tid = threadIdx.x;
    for (int idx = tid; idx < 32 * 32; idx += 256)
        s_w[idx >> 5][idx & 31] = Wt[idx];
    if (tid < 32) s_b[tid] = bias[tid];
    __syncthreads();

    int id = blockIdx.x * 256 + tid;
    if (id >= BB * HWSZ) return;
    int b = id / HWSZ, q = id % HWSZ;

    float x[32];
    #pragma unroll
    for (int ci = 0; ci < 32; ++ci)
        x[ci] = in[((size_t)b * 32 + ci) * HWSZ + q];

    #pragma unroll 4
    for (int oc = 0; oc < 32; ++oc) {
        float s = s_b[oc];
        #pragma unroll
        for (int ci = 0; ci < 32; ++ci)
            s += x[ci] * s_w[oc][ci];
        out[((size_t)b * 32 + oc) * HWSZ + q] = lrelu(s);
    }
}

// ---------------- host launcher ----------------
extern "C" void kernel_launch(void* const* d_in, const int* in_sizes, int n_in,
                              void* d_out, int out_size)
{
    const float* frame   = (const float*)d_in[0];
    const float* srcfr   = (const float*)d_in[1];
    const float* flow_f  = (const float*)d_in[2];
    const float* flow_b  = (const float*)d_in[3];
    const float* W_qk = (const float*)d_in[4];   const float* b_qk = (const float*)d_in[5];
    const float* W_v  = (const float*)d_in[6];   const float* b_v  = (const float*)d_in[7];
    const float* W_vp = (const float*)d_in[8];   const float* b_vp = (const float*)d_in[9];
    const float* W_off= (const float*)d_in[10];  const float* b_off= (const float*)d_in[11];
    const float* W_aw = (const float*)d_in[12];  const float* b_aw = (const float*)d_in[13];
    const float* W_out= (const float*)d_in[14];  const float* b_out= (const float*)d_in[15];
    const float* W_ffd= (const float*)d_in[16];  const float* b_ffd= (const float*)d_in[17];
    const float* W_ff1= (const float*)d_in[18];  const float* b_ff1= (const float*)d_in[19];
    const float* W_ff2= (const float*)d_in[20];  const float* b_ff2= (const float*)d_in[21];
    const float* W_fu = (const float*)d_in[22];  const float* b_fu = (const float*)d_in[23];

    float *qkin, *qureys, *value, *val, *off, *aw, *attn, *out1, *out2, *tseq, *ff1, *out3;
    cudaGetSymbolAddress((void**)&qkin,   g_qkin);
    cudaGetSymbolAddress((void**)&qureys, g_qureys);
    cudaGetSymbolAddress((void**)&value,  g_value);
    cudaGetSymbolAddress((void**)&val,    g_val);
    cudaGetSymbolAddress((void**)&off,    g_off);
    cudaGetSymbolAddress((void**)&aw,     g_aw);
    cudaGetSymbolAddress((void**)&attn,   g_attn);
    cudaGetSymbolAddress((void**)&out1,   g_out1);
    cudaGetSymbolAddress((void**)&out2,   g_out2);
    cudaGetSymbolAddress((void**)&tseq,   g_tseq);
    cudaGetSymbolAddress((void**)&ff1,    g_ff1);
    cudaGetSymbolAddress((void**)&out3,   g_out3);

    // 1. qk_in
    build_qkin_kernel<<<(BB * HWSZ + 255) / 256, 256>>>(frame, flow_f, flow_b, qkin);

    // 2. qureys = lrelu(conv(qk_in, W_qk))      CIN=100 COUT=96
    conv3x3_pipe<100, 1, 1, false><<<dim3(8, 16, BB * 6), 256>>>(
        qkin, W_qk, b_qk, nullptr, 0, qureys, 96);

    // 3. value = conv(frame(96ch), W_v)         CIN=96 COUT=96
    conv3x3_pipe<96, 1, 0, false><<<dim3(8, 16, BB * 6), 256>>>(
        frame, W_v, b_v, nullptr, 0, value, 96);

    // 4. val = conv(value as 6 x 32ch, W_vp)    nimg=6 CIN=32 COUT=32
    conv3x3_pipe<32, 1, 0, false><<<dim3(8, 16, 6 * 2), 256>>>(
        value, W_vp, b_vp, nullptr, 0, val, 32);

    // 5. off = conv(qureys, W_off)              CIN=96 COUT=96
    conv3x3_pipe<96, 1, 0, false><<<dim3(8, 16, BB * 6), 256>>>(
        qureys, W_off, b_off, nullptr, 0, off, 96);

    // 6. aw = conv(qureys, W_aw)                CIN=96 COUT=48
    conv3x3_pipe<96, 1, 0, false><<<dim3(8, 16, BB * 3), 256>>>(
        qureys, W_aw, b_aw, nullptr, 0, aw, 48);

    // 7. deformable attention
    deform_attn_kernel<<<(BB * 4 * HWSZ + 255) / 256, 256>>>(val, off, aw, attn);

    // 8. out1 = conv(attn, W_out)
    conv3x3_pipe<32, 1, 0, false><<<dim3(8, 16, BB * 2), 256>>>(
        attn, W_out, b_out, nullptr, 0, out1, 32);

    // 9. out2 = conv(out1, W_ffd) + frame[:,1]
    conv3x3_pipe<32, 1, 0, true><<<dim3(8, 16, BB * 2), 256>>>(
        out1, W_ffd, b_ffd, frame + (size_t)32 * HWSZ, (size_t)3 * 32 * HWSZ, out2, 32);

    // 10. tseq = concat(out2, srcframe[:,1])
    build_tseq_kernel<<<(BB * 64 * HWSZ + 255) / 256, 256>>>(out2, srcfr, tseq);

    // 11. ff1 = lrelu(conv(tseq, W_ff1, pad=2, dil=2))   CIN=64 COUT=32
    conv3x3_pipe<64, 2, 1, false><<<dim3(8, 16, BB * 2), 256>>>(
        tseq, W_ff1, b_ff1, nullptr, 0, ff1, 32);

    // 12. out3 = conv(ff1, W_ff2) + out2
    conv3x3_pipe<32, 1, 0, true><<<dim3(8, 16, BB * 2), 256>>>(
        ff1, W_ff2, b_ff2, out2, (size_t)32 * HWSZ, out3, 32);

    // 13. out = lrelu(conv1x1(out3, W_fu))
    conv1x1_lrelu_kernel<<<(BB * HWSZ + 255) / 256, 256>>>(out3, W_fu, b_fu, (float*)d_out);
}

// round 5
// speedup vs baseline: 1.0013x; 1.0013x over previous
#include <cuda_runtime.h>
#include <cstdint>
#include <math.h>

constexpr int IMH = 256, IMW = 256;
constexpr int HWSZ = IMH * IMW;       // 65536
constexpr int BB = 2;

// ---------------- scratch (device globals; no runtime allocation) ----------------
__device__ float g_qkin  [(size_t)BB * 100 * HWSZ];
__device__ float g_qureys[(size_t)BB *  96 * HWSZ];
__device__ float g_value [(size_t)BB *  96 * HWSZ];
__device__ float g_val   [(size_t)BB *  96 * HWSZ];
__device__ float g_off   [(size_t)BB *  96 * HWSZ];
__device__ float g_aw    [(size_t)BB *  48 * HWSZ];
__device__ float g_attn  [(size_t)BB *  32 * HWSZ];
__device__ float g_out1  [(size_t)BB *  32 * HWSZ];
__device__ float g_out2  [(size_t)BB *  32 * HWSZ];
__device__ float g_tseq  [(size_t)BB *  64 * HWSZ];
__device__ float g_ff1   [(size_t)BB *  32 * HWSZ];
__device__ float g_out3  [(size_t)BB *  32 * HWSZ];

__device__ __forceinline__ float lrelu(float v) { return v >= 0.f ? v : 0.1f * v; }

// ---------------- packed f32x2 helpers (Blackwell FFMA2) ----------------
__device__ __forceinline__ void ffma2(unsigned long long& acc, unsigned long long x,
                                      unsigned long long w)
{
    asm("fma.rn.f32x2 %0, %1, %2, %0;" : "+l"(acc) : "l"(x), "l"(w));
}
__device__ __forceinline__ unsigned long long packf2(float lo, float hi)
{
    unsigned long long r;
    asm("mov.b64 %0, {%1, %2};" : "=l"(r) : "f"(lo), "f"(hi));
    return r;
}
__device__ __forceinline__ void unpackf2(unsigned long long v, float& lo, float& hi)
{
    asm("mov.b64 {%0, %1}, %2;" : "=f"(lo), "=f"(hi) : "l"(v));
}

// ---------------- kernel 1: build qk_in (flow warps + concat) ----------------
__device__ __forceinline__ void sample32(const float* __restrict__ img, float sx, float sy,
                                         float* __restrict__ dst, int q)
{
    float x0f = floorf(sx), y0f = floorf(sy);
    float lx = sx - x0f, ly = sy - y0f;
    int x0 = (int)x0f, y0 = (int)y0f;
    float w00 = (1.f - lx) * (1.f - ly);
    float w01 = lx * (1.f - ly);
    float w10 = (1.f - lx) * ly;
    float w11 = lx * ly;
    bool vx0 = (unsigned)x0       < (unsigned)IMW;
    bool vx1 = (unsigned)(x0 + 1) < (unsigned)IMW;
    bool vy0 = (unsigned)y0       < (unsigned)IMH;
    bool vy1 = (unsigned)(y0 + 1) < (unsigned)IMH;
    int cx0 = min(max(x0, 0), IMW - 1), cx1 = min(max(x0 + 1, 0), IMW - 1);
    int cy0 = min(max(y0, 0), IMH - 1), cy1 = min(max(y0 + 1, 0), IMH - 1);
    int i00 = cy0 * IMW + cx0, i01 = cy0 * IMW + cx1;
    int i10 = cy1 * IMW + cx0, i11 = cy1 * IMW + cx1;
    float m00 = (vx0 && vy0) ? w00 : 0.f;
    float m01 = (vx1 && vy0) ? w01 : 0.f;
    float m10 = (vx0 && vy1) ? w10 : 0.f;
    float m11 = (vx1 && vy1) ? w11 : 0.f;
    #pragma unroll 4
    for (int c = 0; c < 32; ++c) {
        const float* p = img + (size_t)c * HWSZ;
        dst[(size_t)c * HWSZ + q] = m00 * p[i00] + m01 * p[i01] + m10 * p[i10] + m11 * p[i11];
    }
}

__global__ void build_qkin_kernel(const float* __restrict__ frame,
                                  const float* __restrict__ flow_f,
                                  const float* __restrict__ flow_b,
                                  float* __restrict__ qkin)
{
    int id = blockIdx.x * blockDim.x + threadIdx.x;
    if (id >= BB * HWSZ) return;
    int b = id / HWSZ, q = id % HWSZ;
    int px = q & (IMW - 1), py = q >> 8;

    const float* fb = flow_b + (size_t)b * 2 * 2 * HWSZ;
    float fbx = fb[q], fby = fb[HWSZ + q];
    const float* ff = flow_f + (size_t)b * 2 * 2 * HWSZ + (size_t)2 * HWSZ;
    float ffx = ff[q], ffy = ff[HWSZ + q];

    float* dst = qkin + (size_t)b * 100 * HWSZ;
    sample32(frame + ((size_t)b * 3 + 0) * 32 * HWSZ, (float)px + fbx, (float)py + fby, dst, q);
    const float* f1 = frame + ((size_t)b * 3 + 1) * 32 * HWSZ;
    #pragma unroll 4
    for (int c = 0; c < 32; ++c)
        dst[(size_t)(32 + c) * HWSZ + q] = f1[(size_t)c * HWSZ + q];
    sample32(frame + ((size_t)b * 3 + 2) * 32 * HWSZ, (float)px + ffx, (float)py + ffy,
             dst + (size_t)64 * HWSZ, q);
    dst[(size_t)96 * HWSZ + q] = ffx;
    dst[(size_t)97 * HWSZ + q] = ffy;
    dst[(size_t)98 * HWSZ + q] = fbx;
    dst[(size_t)99 * HWSZ + q] = fby;
}

// ---------------- cp.async helpers ----------------
__device__ __forceinline__ void cpasync4(unsigned int dst, const float* src, bool ok)
{
    int sz = ok ? 4 : 0;
    asm volatile("cp.async.ca.shared.global [%0], [%1], 4, %2;\n"
                 :: "r"(dst), "l"(src), "r"(sz));
}
__device__ __forceinline__ void cpasync_commit() {
    asm volatile("cp.async.commit_group;\n" ::: "memory");
}
__device__ __forceinline__ void cpasync_wait0() {
    asm volatile("cp.async.wait_group 0;\n" ::: "memory");
}

// ---------------- pipelined tiled 3x3 conv, packed-FFMA2 mainloop ----------------
// tile: 32(x) x 16(y) output pixels, 16 out channels per block,
// each thread: 2 pixels (rows py, py+8) x 16 oc, acc as f32x2 pairs.
// Weights duplicated (w,w) in smem so LDS.128 yields two broadcast pairs.
template<int CIN, int DIL, int ACT, bool RES>
__global__ void __launch_bounds__(256, 3) conv3x3_pipe(
    const float* __restrict__ in, const float* __restrict__ Wt,
    const float* __restrict__ bias, const float* __restrict__ res, size_t resStride,
    float* __restrict__ out, int COUT)
{
    constexpr int TX = 32, TY = 16, OCB = 16;
    constexpr int IW = TX + 2 * DIL, IH = TY + 2 * DIL;
    constexpr int NCH = CIN / 4;
    constexpr int TILE_ELEMS = 4 * IH * IW;
    __shared__ float s_in[2][4][IH][IW];
    __shared__ __align__(16) float2 s_w[2][4][9][OCB];   // (w,w) duplicated

    const int tid = threadIdx.x;
    const int px = tid & 31, py = tid >> 5;          // px 0..31, py 0..7
    const int x0 = blockIdx.x * TX, y0 = blockIdx.y * TY;
    const int ngrp = COUT >> 4;
    const int img = blockIdx.z / ngrp;
    const int ocBase = (blockIdx.z % ngrp) * OCB;
    const float* inImg = in + (size_t)img * CIN * HWSZ;

    unsigned long long accP[OCB];
    #pragma unroll
    for (int i = 0; i < OCB; ++i) accP[i] = 0ULL;

    // ---- prologue: chunk 0 into buffer 0 ----
    {
        #pragma unroll 4
        for (int idx = tid; idx < TILE_ELEMS; idx += 256) {
            int ci = idx / (IH * IW);
            int rem = idx % (IH * IW);
            int ly = rem / IW, lx = rem % IW;
            int gy = y0 - DIL + ly, gx = x0 - DIL + lx;
            bool ok = ((unsigned)gy < (unsigned)IMH) && ((unsigned)gx < (unsigned)IMW);
            int cgy = ok ? gy : 0, cgx = ok ? gx : 0;
            const float* src = inImg + (size_t)ci * HWSZ + cgy * IMW + cgx;
            unsigned int dst = (unsigned int)__cvta_generic_to_shared(&s_in[0][ci][ly][lx]);
            cpasync4(dst, src, ok);
        }
        cpasync_commit();
        #pragma unroll 3
        for (int idx = tid; idx < 4 * 9 * OCB; idx += 256) {
            int oc = idx & 15;
            int k  = (idx >> 4) % 9;
            int ci = (idx >> 4) / 9;
            float w = Wt[((size_t)(ocBase + oc) * CIN + ci) * 9 + k];
            s_w[0][ci][k][oc] = make_float2(w, w);
        }
        cpasync_wait0();
        __syncthreads();
    }

    int buf = 0;
    #pragma unroll 1
    for (int cc = 0; cc < NCH; ++cc) {
        // ---- prefetch next chunk into buf^1 ----
        if (cc + 1 < NCH) {
            const int nb = buf ^ 1;
            const int ciBase = (cc + 1) * 4;
            #pragma unroll 4
            for (int idx = tid; idx < TILE_ELEMS; idx += 256) {
                int ci = idx / (IH * IW);
                int rem = idx % (IH * IW);
                int ly = rem / IW, lx = rem % IW;
                int gy = y0 - DIL + ly, gx = x0 - DIL + lx;
                bool ok = ((unsigned)gy < (unsigned)IMH) && ((unsigned)gx < (unsigned)IMW);
                int cgy = ok ? gy : 0, cgx = ok ? gx : 0;
                const float* src = inImg + (size_t)(ciBase + ci) * HWSZ + cgy * IMW + cgx;
                unsigned int dst = (unsigned int)__cvta_generic_to_shared(&s_in[nb][ci][ly][lx]);
                cpasync4(dst, src, ok);
            }
            #pragma unroll 3
            for (int idx = tid; idx < 4 * 9 * OCB; idx += 256) {
                int oc = idx & 15;
                int k  = (idx >> 4) % 9;
                int ci = (idx >> 4) / 9;
                float w = Wt[((size_t)(ocBase + oc) * CIN + ciBase + ci) * 9 + k];
                s_w[nb][ci][k][oc] = make_float2(w, w);
            }
        }
        cpasync_commit();

        // ---- compute current chunk (packed FFMA2) ----
        #pragma unroll
        for (int ci = 0; ci < 4; ++ci) {
            #pragma unroll
            for (int k = 0; k < 9; ++k) {
                const int ky = k / 3, kx = k % 3;
                float xa = s_in[buf][ci][py +     ky * DIL][px + kx * DIL];
                float xb = s_in[buf][ci][py + 8 + ky * DIL][px + kx * DIL];
                unsigned long long xp = packf2(xa, xb);
                const ulonglong2* wp = reinterpret_cast<const ulonglong2*>(&s_w[buf][ci][k][0]);
                #pragma unroll
                for (int o2 = 0; o2 < 8; ++o2) {
                    ulonglong2 w2 = wp[o2];
                    ffma2(accP[o2 * 2 + 0], xp, w2.x);
                    ffma2(accP[o2 * 2 + 1], xp, w2.y);
                }
            }
        }

        cpasync_wait0();
        __syncthreads();
        buf ^= 1;
    }

    const int ox = x0 + px;
    const int oyA = y0 + py, oyB = y0 + py + 8;
    const size_t outImg = (size_t)img * COUT * HWSZ;
    #pragma unroll
    for (int oc = 0; oc < OCB; ++oc) {
        float vA, vB;
        unpackf2(accP[oc], vA, vB);
        float bv = bias[ocBase + oc];
        vA += bv;
        vB += bv;
        if (RES) {
            const float* rp = res + (size_t)img * resStride + (size_t)(ocBase + oc) * HWSZ;
            vA += rp[oyA * IMW + ox];
            vB += rp[oyB * IMW + ox];
        }
        if (ACT) { vA = lrelu(vA); vB = lrelu(vB); }
        size_t chOff = outImg + (size_t)(ocBase + oc) * HWSZ;
        out[chOff + oyA * IMW + ox] = vA;
        out[chOff + oyB * IMW + ox] = vB;
    }
}

// ---------------- deformable attention ----------------
__global__ void deform_attn_kernel(const float* __restrict__ val,
                                   const float* __restrict__ off,
                                   const float* __restrict__ awl,
                                   float* __restrict__ out)
{
    int id = blockIdx.x * blockDim.x + threadIdx.x;
    if (id >= BB * 4 * HWSZ) return;
    int q = id % HWSZ;
    int head = (id / HWSZ) & 3;
    int b = id / (4 * HWSZ);
    int px = q & (IMW - 1), py = q >> 8;

    const float* awp = awl + ((size_t)b * 48 + head * 12) * HWSZ + q;
    float lg[12];
    float mx = -1e30f;
    #pragma unroll
    for (int i = 0; i < 12; ++i) { lg[i] = awp[(size_t)i * HWSZ]; mx = fmaxf(mx, lg[i]); }
    float s = 0.f;
    #pragma unroll
    for (int i = 0; i < 12; ++i) { lg[i] = expf(lg[i] - mx); s += lg[i]; }
    float inv = 1.f / s;

    float acc[8];
    #pragma unroll
    for (int e = 0; e < 8; ++e) acc[e] = 0.f;

    const float* offp = off + ((size_t)b * 96 + head * 24) * HWSZ + q;

    for (int l = 0; l < 3; ++l) {
        const float* vbase = val + (((size_t)b * 3 + l) * 32 + head * 8) * HWSZ;
        #pragma unroll
        for (int p = 0; p < 4; ++p) {
            int ch = (l * 4 + p) * 2;
            float sx = (float)px + offp[(size_t)ch * HWSZ];
            float sy = (float)py + offp[(size_t)(ch + 1) * HWSZ];
            float a = lg[l * 4 + p] * inv;

            float x0f = floorf(sx), y0f = floorf(sy);
            float lx = sx - x0f, ly = sy - y0f;
            int x0 = (int)x0f, y0 = (int)y0f;
            float w00 = (1.f - lx) * (1.f - ly);
            float w01 = lx * (1.f - ly);
            float w10 = (1.f - lx) * ly;
            float w11 = lx * ly;
            bool vx0 = (unsigned)x0       < (unsigned)IMW;
            bool vx1 = (unsigned)(x0 + 1) < (unsigned)IMW;
            bool vy0 = (unsigned)y0       < (unsigned)IMH;
            bool vy1 = (unsigned)(y0 + 1) < (unsigned)IMH;
            int cx0 = min(max(x0, 0), IMW - 1), cx1 = min(max(x0 + 1, 0), IMW - 1);
            int cy0 = min(max(y0, 0), IMH - 1), cy1 = min(max(y0 + 1, 0), IMH - 1);
            float c00 = (vx0 && vy0) ? a * w00 : 0.f;
            float c01 = (vx1 && vy0) ? a * w01 : 0.f;
            float c10 = (vx0 && vy1) ? a * w10 : 0.f;
            float c11 = (vx1 && vy1) ? a * w11 : 0.f;
            int i00 = cy0 * IMW + cx0, i01 = cy0 * IMW + cx1;
            int i10 = cy1 * IMW + cx0, i11 = cy1 * IMW + cx1;
            #pragma unroll
            for (int e = 0; e < 8; ++e) {
                const float* vp = vbase + (size_t)e * HWSZ;
                acc[e] += c00 * vp[i00] + c01 * vp[i01] + c10 * vp[i10] + c11 * vp[i11];
            }
        }
    }

    float* op = out + ((size_t)b * 32 + head * 8) * HWSZ + q;
    #pragma unroll
    for (int e = 0; e < 8; ++e) op[(size_t)e * HWSZ] = acc[e];
}

// ---------------- concat [out2, srcframe[:,1]] ----------------
__global__ void build_tseq_kernel(const float* __restrict__ out2,
                                  const float* __restrict__ srcframe,
                                  float* __restrict__ tseq)
{
    int id = blockIdx.x * blockDim.x + threadIdx.x;
    if (id >= BB * 64 * HWSZ) return;
    int q = id % HWSZ;
    int c = (id / HWSZ) & 63;
    int b = id / (64 * HWSZ);
    float v;
    if (c < 32) v = out2[((size_t)b * 32 + c) * HWSZ + q];
    else        v = srcframe[(((size_t)b * 3 + 1) * 32 + (c - 32)) * HWSZ + q];
    tseq[((size_t)b * 64 + c) * HWSZ + q] = v;
}

// ---------------- final 1x1 conv + lrelu ----------------
__global__ void conv1x1_lrelu_kernel(const float* __restrict__ in,
                                     const float* __restrict__ Wt,
                                     const float* __restrict__ bias,
                                     float* __restrict__ out)
{
    __shared__ float s_w[32][32];
    __shared__ float s_b[32];
    int tid = threadIdx.x;
    for (int idx = tid; idx < 32 * 32; idx += 256)
        s_w[idx >> 5][idx & 31] = Wt[idx];
    if (tid < 32) s_b[tid] = bias[tid];
    __syncthreads();

    int id = blockIdx.x * 256 + tid;
    if (id >= BB * HWSZ) return;
    int b = id / HWSZ, q = id % HWSZ;

    float x[32];
    #pragma unroll
    for (int ci = 0; ci < 32; ++ci)
        x[ci] = in[((size_t)b * 32 + ci) * HWSZ + q];

    #pragma unroll 4
    for (int oc = 0; oc < 32; ++oc) {
        float s = s_b[oc];
        #pragma unroll
        for (int ci = 0; ci < 32; ++ci)
            s += x[ci] * s_w[oc][ci];
        out[((size_t)b * 32 + oc) * HWSZ + q] = lrelu(s);
    }
}

// ---------------- host launcher ----------------
extern "C" void kernel_launch(void* const* d_in, const int* in_sizes, int n_in,
                              void* d_out, int out_size)
{
    const float* frame   = (const float*)d_in[0];
    const float* srcfr   = (const float*)d_in[1];
    const float* flow_f  = (const float*)d_in[2];
    const float* flow_b  = (const float*)d_in[3];
    const float* W_qk = (const float*)d_in[4];   const float* b_qk = (const float*)d_in[5];
    const float* W_v  = (const float*)d_in[6];   const float* b_v  = (const float*)d_in[7];
    const float* W_vp = (const float*)d_in[8];   const float* b_vp = (const float*)d_in[9];
    const float* W_off= (const float*)d_in[10];  const float* b_off= (const float*)d_in[11];
    const float* W_aw = (const float*)d_in[12];  const float* b_aw = (const float*)d_in[13];
    const float* W_out= (const float*)d_in[14];  const float* b_out= (const float*)d_in[15];
    const float* W_ffd= (const float*)d_in[16];  const float* b_ffd= (const float*)d_in[17];
    const float* W_ff1= (const float*)d_in[18];  const float* b_ff1= (const float*)d_in[19];
    const float* W_ff2= (const float*)d_in[20];  const float* b_ff2= (const float*)d_in[21];
    const float* W_fu = (const float*)d_in[22];  const float* b_fu = (const float*)d_in[23];

    float *qkin, *qureys, *value, *val, *off, *aw, *attn, *out1, *out2, *tseq, *ff1, *out3;
    cudaGetSymbolAddress((void**)&qkin,   g_qkin);
    cudaGetSymbolAddress((void**)&qureys, g_qureys);
    cudaGetSymbolAddress((void**)&value,  g_value);
    cudaGetSymbolAddress((void**)&val,    g_val);
    cudaGetSymbolAddress((void**)&off,    g_off);
    cudaGetSymbolAddress((void**)&aw,     g_aw);
    cudaGetSymbolAddress((void**)&attn,   g_attn);
    cudaGetSymbolAddress((void**)&out1,   g_out1);
    cudaGetSymbolAddress((void**)&out2,   g_out2);
    cudaGetSymbolAddress((void**)&tseq,   g_tseq);
    cudaGetSymbolAddress((void**)&ff1,    g_ff1);
    cudaGetSymbolAddress((void**)&out3,   g_out3);

    // 1. qk_in
    build_qkin_kernel<<<(BB * HWSZ + 255) / 256, 256>>>(frame, flow_f, flow_b, qkin);

    // 2. qureys = lrelu(conv(qk_in, W_qk))      CIN=100 COUT=96
    conv3x3_pipe<100, 1, 1, false><<<dim3(8, 16, BB * 6), 256>>>(
        qkin, W_qk, b_qk, nullptr, 0, qureys, 96);

    // 3. value = conv(frame(96ch), W_v)         CIN=96 COUT=96
    conv3x3_pipe<96, 1, 0, false><<<dim3(8, 16, BB * 6), 256>>>(
        frame, W_v, b_v, nullptr, 0, value, 96);

    // 4. val = conv(value as 6 x 32ch, W_vp)    nimg=6 CIN=32 COUT=32
    conv3x3_pipe<32, 1, 0, false><<<dim3(8, 16, 6 * 2), 256>>>(
        value, W_vp, b_vp, nullptr, 0, val, 32);

    // 5. off = conv(qureys, W_off)              CIN=96 COUT=96
    conv3x3_pipe<96, 1, 0, false><<<dim3(8, 16, BB * 6), 256>>>(
        qureys, W_off, b_off, nullptr, 0, off, 96);

    // 6. aw = conv(qureys, W_aw)                CIN=96 COUT=48
    conv3x3_pipe<96, 1, 0, false><<<dim3(8, 16, BB * 3), 256>>>(
        qureys, W_aw, b_aw, nullptr, 0, aw, 48);

    // 7. deformable attention
    deform_attn_kernel<<<(BB * 4 * HWSZ + 255) / 256, 256>>>(val, off, aw, attn);

    // 8. out1 = conv(attn, W_out)
    conv3x3_pipe<32, 1, 0, false><<<dim3(8, 16, BB * 2), 256>>>(
        attn, W_out, b_out, nullptr, 0, out1, 32);

    // 9. out2 = conv(out1, W_ffd) + frame[:,1]
    conv3x3_pipe<32, 1, 0, true><<<dim3(8, 16, BB * 2), 256>>>(
        out1, W_ffd, b_ffd, frame + (size_t)32 * HWSZ, (size_t)3 * 32 * HWSZ, out2, 32);

    // 10. tseq = concat(out2, srcframe[:,1])
    build_tseq_kernel<<<(BB * 64 * HWSZ + 255) / 256, 256>>>(out2, srcfr, tseq);

    // 11. ff1 = lrelu(conv(tseq, W_ff1, pad=2, dil=2))   CIN=64 COUT=32
    conv3x3_pipe<64, 2, 1, false><<<dim3(8, 16, BB * 2), 256>>>(
        tseq, W_ff1, b_ff1, nullptr, 0, ff1, 32);

    // 12. out3 = conv(ff1, W_ff2) + out2
    conv3x3_pipe<32, 1, 0, true><<<dim3(8, 16, BB * 2), 256>>>(
        ff1, W_ff2, b_ff2, out2, (size_t)32 * HWSZ, out3, 32);

    // 13. out = lrelu(conv1x1(out3, W_fu))
    conv1x1_lrelu_kernel<<<(BB * HWSZ + 255) / 256, 256>>>(out3, W_fu, b_fu, (float*)d_out);
}

// round 6
// speedup vs baseline: 1.3826x; 1.3808x over previous
#include <cuda_runtime.h>
#include <cstdint>
#include <math.h>

constexpr int IMH = 256, IMW = 256;
constexpr int HWSZ = IMH * IMW;       // 65536
constexpr int BB = 2;

// ---------------- scratch (device globals; no runtime allocation) ----------------
__device__ float g_qkin  [(size_t)BB * 100 * HWSZ];
__device__ float g_qureys[(size_t)BB *  96 * HWSZ];
__device__ float g_value [(size_t)BB *  96 * HWSZ];
__device__ float g_val   [(size_t)BB *  96 * HWSZ];
__device__ float g_off   [(size_t)BB *  96 * HWSZ];
__device__ float g_aw    [(size_t)BB *  48 * HWSZ];
__device__ float g_attn  [(size_t)BB *  32 * HWSZ];
__device__ float g_out1  [(size_t)BB *  32 * HWSZ];
__device__ float g_out2  [(size_t)BB *  32 * HWSZ];
__device__ float g_tseq  [(size_t)BB *  64 * HWSZ];
__device__ float g_ff1   [(size_t)BB *  32 * HWSZ];
__device__ float g_out3  [(size_t)BB *  32 * HWSZ];

__device__ __forceinline__ float lrelu(float v) { return v >= 0.f ? v : 0.1f * v; }

// ---------------- packed f32x2 helpers (Blackwell FFMA2) ----------------
__device__ __forceinline__ void ffma2(unsigned long long& acc, unsigned long long x,
                                      unsigned long long w)
{
    asm("fma.rn.f32x2 %0, %1, %2, %0;" : "+l"(acc) : "l"(x), "l"(w));
}
__device__ __forceinline__ unsigned long long packf2(float lo, float hi)
{
    unsigned long long r;
    asm("mov.b64 %0, {%1, %2};" : "=l"(r) : "f"(lo), "f"(hi));
    return r;
}
__device__ __forceinline__ void unpackf2(unsigned long long v, float& lo, float& hi)
{
    asm("mov.b64 {%0, %1}, %2;" : "=f"(lo), "=f"(hi) : "l"(v));
}

// ---------------- kernel 1: build qk_in (flow warps + concat) ----------------
__device__ __forceinline__ void sample32(const float* __restrict__ img, float sx, float sy,
                                         float* __restrict__ dst, int q)
{
    float x0f = floorf(sx), y0f = floorf(sy);
    float lx = sx - x0f, ly = sy - y0f;
    int x0 = (int)x0f, y0 = (int)y0f;
    float w00 = (1.f - lx) * (1.f - ly);
    float w01 = lx * (1.f - ly);
    float w10 = (1.f - lx) * ly;
    float w11 = lx * ly;
    bool vx0 = (unsigned)x0       < (unsigned)IMW;
    bool vx1 = (unsigned)(x0 + 1) < (unsigned)IMW;
    bool vy0 = (unsigned)y0       < (unsigned)IMH;
    bool vy1 = (unsigned)(y0 + 1) < (unsigned)IMH;
    int cx0 = min(max(x0, 0), IMW - 1), cx1 = min(max(x0 + 1, 0), IMW - 1);
    int cy0 = min(max(y0, 0), IMH - 1), cy1 = min(max(y0 + 1, 0), IMH - 1);
    int i00 = cy0 * IMW + cx0, i01 = cy0 * IMW + cx1;
    int i10 = cy1 * IMW + cx0, i11 = cy1 * IMW + cx1;
    float m00 = (vx0 && vy0) ? w00 : 0.f;
    float m01 = (vx1 && vy0) ? w01 : 0.f;
    float m10 = (vx0 && vy1) ? w10 : 0.f;
    float m11 = (vx1 && vy1) ? w11 : 0.f;
    #pragma unroll 4
    for (int c = 0; c < 32; ++c) {
        const float* p = img + (size_t)c * HWSZ;
        dst[(size_t)c * HWSZ + q] = m00 * p[i00] + m01 * p[i01] + m10 * p[i10] + m11 * p[i11];
    }
}

__global__ void build_qkin_kernel(const float* __restrict__ frame,
                                  const float* __restrict__ flow_f,
                                  const float* __restrict__ flow_b,
                                  float* __restrict__ qkin)
{
    int id = blockIdx.x * blockDim.x + threadIdx.x;
    if (id >= BB * HWSZ) return;
    int b = id / HWSZ, q = id % HWSZ;
    int px = q & (IMW - 1), py = q >> 8;

    const float* fb = flow_b + (size_t)b * 2 * 2 * HWSZ;
    float fbx = fb[q], fby = fb[HWSZ + q];
    const float* ff = flow_f + (size_t)b * 2 * 2 * HWSZ + (size_t)2 * HWSZ;
    float ffx = ff[q], ffy = ff[HWSZ + q];

    float* dst = qkin + (size_t)b * 100 * HWSZ;
    sample32(frame + ((size_t)b * 3 + 0) * 32 * HWSZ, (float)px + fbx, (float)py + fby, dst, q);
    const float* f1 = frame + ((size_t)b * 3 + 1) * 32 * HWSZ;
    #pragma unroll 4
    for (int c = 0; c < 32; ++c)
        dst[(size_t)(32 + c) * HWSZ + q] = f1[(size_t)c * HWSZ + q];
    sample32(frame + ((size_t)b * 3 + 2) * 32 * HWSZ, (float)px + ffx, (float)py + ffy,
             dst + (size_t)64 * HWSZ, q);
    dst[(size_t)96 * HWSZ + q] = ffx;
    dst[(size_t)97 * HWSZ + q] = ffy;
    dst[(size_t)98 * HWSZ + q] = fbx;
    dst[(size_t)99 * HWSZ + q] = fby;
}

// ---------------- cp.async helpers ----------------
__device__ __forceinline__ void cpasync4(unsigned int dst, const float* src, bool ok)
{
    int sz = ok ? 4 : 0;
    asm volatile("cp.async.ca.shared.global [%0], [%1], 4, %2;\n"
                 :: "r"(dst), "l"(src), "r"(sz));
}
__device__ __forceinline__ void cpasync_commit() {
    asm volatile("cp.async.commit_group;\n" ::: "memory");
}
__device__ __forceinline__ void cpasync_wait0() {
    asm volatile("cp.async.wait_group 0;\n" ::: "memory");
}

// ---------------- pipelined tiled 3x3 conv, FFMA2 over oc-pairs ----------------
// tile: 32(x) x 16(y) output pixels, 16 out channels per block,
// each thread: 2 pixels (rows py, py+8) x 16 oc.
// Accumulators are f32x2 over ADJACENT OUTPUT CHANNELS; pixel value is
// broadcast-packed (x,x) in registers. Weights stored in natural order.
template<int CIN, int DIL, int ACT, bool RES>
__global__ void __launch_bounds__(256, 3) conv3x3_pipe(
    const float* __restrict__ in, const float* __restrict__ Wt,
    const float* __restrict__ bias, const float* __restrict__ res, size_t resStride,
    float* __restrict__ out, int COUT)
{
    constexpr int TX = 32, TY = 16, OCB = 16;
    constexpr int IW = TX + 2 * DIL, IH = TY + 2 * DIL;
    constexpr int NCH = CIN / 4;
    constexpr int TILE_ELEMS = 4 * IH * IW;
    __shared__ float s_in[2][4][IH][IW];
    __shared__ __align__(16) float s_w[2][4][9][OCB];   // natural order

    const int tid = threadIdx.x;
    const int px = tid & 31, py = tid >> 5;          // px 0..31, py 0..7
    const int x0 = blockIdx.x * TX, y0 = blockIdx.y * TY;
    const int ngrp = COUT >> 4;
    const int img = blockIdx.z / ngrp;
    const int ocBase = (blockIdx.z % ngrp) * OCB;
    const float* inImg = in + (size_t)img * CIN * HWSZ;

    // accA[j]/accB[j] hold oc pair (2j, 2j+1) for pixel rows py / py+8
    unsigned long long accA[8], accB[8];
    #pragma unroll
    for (int i = 0; i < 8; ++i) { accA[i] = 0ULL; accB[i] = 0ULL; }

    // ---- prologue: chunk 0 into buffer 0 ----
    {
        #pragma unroll 4
        for (int idx = tid; idx < TILE_ELEMS; idx += 256) {
            int ci = idx / (IH * IW);
            int rem = idx % (IH * IW);
            int ly = rem / IW, lx = rem % IW;
            int gy = y0 - DIL + ly, gx = x0 - DIL + lx;
            bool ok = ((unsigned)gy < (unsigned)IMH) && ((unsigned)gx < (unsigned)IMW);
            int cgy = ok ? gy : 0, cgx = ok ? gx : 0;
            const float* src = inImg + (size_t)ci * HWSZ + cgy * IMW + cgx;
            unsigned int dst = (unsigned int)__cvta_generic_to_shared(&s_in[0][ci][ly][lx]);
            cpasync4(dst, src, ok);
        }
        cpasync_commit();
        #pragma unroll 3
        for (int idx = tid; idx < 4 * 9 * OCB; idx += 256) {
            int oc = idx & 15;
            int k  = (idx >> 4) % 9;
            int ci = (idx >> 4) / 9;
            s_w[0][ci][k][oc] = Wt[((size_t)(ocBase + oc) * CIN + ci) * 9 + k];
        }
        cpasync_wait0();
        __syncthreads();
    }

    int buf = 0;
    #pragma unroll 1
    for (int cc = 0; cc < NCH; ++cc) {
        // ---- prefetch next chunk into buf^1 ----
        if (cc + 1 < NCH) {
            const int nb = buf ^ 1;
            const int ciBase = (cc + 1) * 4;
            #pragma unroll 4
            for (int idx = tid; idx < TILE_ELEMS; idx += 256) {
                int ci = idx / (IH * IW);
                int rem = idx % (IH * IW);
                int ly = rem / IW, lx = rem % IW;
                int gy = y0 - DIL + ly, gx = x0 - DIL + lx;
                bool ok = ((unsigned)gy < (unsigned)IMH) && ((unsigned)gx < (unsigned)IMW);
                int cgy = ok ? gy : 0, cgx = ok ? gx : 0;
                const float* src = inImg + (size_t)(ciBase + ci) * HWSZ + cgy * IMW + cgx;
                unsigned int dst = (unsigned int)__cvta_generic_to_shared(&s_in[nb][ci][ly][lx]);
                cpasync4(dst, src, ok);
            }
            #pragma unroll 3
            for (int idx = tid; idx < 4 * 9 * OCB; idx += 256) {
                int oc = idx & 15;
                int k  = (idx >> 4) % 9;
                int ci = (idx >> 4) / 9;
                s_w[nb][ci][k][oc] = Wt[((size_t)(ocBase + oc) * CIN + ciBase + ci) * 9 + k];
            }
        }
        cpasync_commit();

        // ---- compute current chunk (FFMA2 over oc-pairs) ----
        #pragma unroll
        for (int ci = 0; ci < 4; ++ci) {
            #pragma unroll
            for (int k = 0; k < 9; ++k) {
                const int ky = k / 3, kx = k % 3;
                float xa = s_in[buf][ci][py +     ky * DIL][px + kx * DIL];
                float xb = s_in[buf][ci][py + 8 + ky * DIL][px + kx * DIL];
                unsigned long long xpa = packf2(xa, xa);
                unsigned long long xpb = packf2(xb, xb);
                const ulonglong2* wp = reinterpret_cast<const ulonglong2*>(&s_w[buf][ci][k][0]);
                #pragma unroll
                for (int o4 = 0; o4 < 4; ++o4) {
                    ulonglong2 w2 = wp[o4];   // oc pairs (4o4,4o4+1) and (4o4+2,4o4+3)
                    ffma2(accA[o4 * 2 + 0], xpa, w2.x);
                    ffma2(accA[o4 * 2 + 1], xpa, w2.y);
                    ffma2(accB[o4 * 2 + 0], xpb, w2.x);
                    ffma2(accB[o4 * 2 + 1], xpb, w2.y);
                }
            }
        }

        cpasync_wait0();
        __syncthreads();
        buf ^= 1;
    }

    const int ox = x0 + px;
    const int oyA = y0 + py, oyB = y0 + py + 8;
    const size_t outImg = (size_t)img * COUT * HWSZ;
    #pragma unroll
    for (int j = 0; j < 8; ++j) {
        float a0, a1, b0, b1;
        unpackf2(accA[j], a0, a1);
        unpackf2(accB[j], b0, b1);
        #pragma unroll
        for (int h = 0; h < 2; ++h) {
            int oc = j * 2 + h;
            float vA = (h ? a1 : a0);
            float vB = (h ? b1 : b0);
            float bv = bias[ocBase + oc];
            vA += bv;
            vB += bv;
            if (RES) {
                const float* rp = res + (size_t)img * resStride + (size_t)(ocBase + oc) * HWSZ;
                vA += rp[oyA * IMW + ox];
                vB += rp[oyB * IMW + ox];
            }
            if (ACT) { vA = lrelu(vA); vB = lrelu(vB); }
            size_t chOff = outImg + (size_t)(ocBase + oc) * HWSZ;
            out[chOff + oyA * IMW + ox] = vA;
            out[chOff + oyB * IMW + ox] = vB;
        }
    }
}

// ---------------- deformable attention ----------------
__global__ void deform_attn_kernel(const float* __restrict__ val,
                                   const float* __restrict__ off,
                                   const float* __restrict__ awl,
                                   float* __restrict__ out)
{
    int id = blockIdx.x * blockDim.x + threadIdx.x;
    if (id >= BB * 4 * HWSZ) return;
    int q = id % HWSZ;
    int head = (id / HWSZ) & 3;
    int b = id / (4 * HWSZ);
    int px = q & (IMW - 1), py = q >> 8;

    const float* awp = awl + ((size_t)b * 48 + head * 12) * HWSZ + q;
    float lg[12];
    float mx = -1e30f;
    #pragma unroll
    for (int i = 0; i < 12; ++i) { lg[i] = awp[(size_t)i * HWSZ]; mx = fmaxf(mx, lg[i]); }
    float s = 0.f;
    #pragma unroll
    for (int i = 0; i < 12; ++i) { lg[i] = expf(lg[i] - mx); s += lg[i]; }
    float inv = 1.f / s;

    float acc[8];
    #pragma unroll
    for (int e = 0; e < 8; ++e) acc[e] = 0.f;

    const float* offp = off + ((size_t)b * 96 + head * 24) * HWSZ + q;

    for (int l = 0; l < 3; ++l) {
        const float* vbase = val + (((size_t)b * 3 + l) * 32 + head * 8) * HWSZ;
        #pragma unroll
        for (int p = 0; p < 4; ++p) {
            int ch = (l * 4 + p) * 2;
            float sx = (float)px + offp[(size_t)ch * HWSZ];
            float sy = (float)py + offp[(size_t)(ch + 1) * HWSZ];
            float a = lg[l * 4 + p] * inv;

            float x0f = floorf(sx), y0f = floorf(sy);
            float lx = sx - x0f, ly = sy - y0f;
            int x0 = (int)x0f, y0 = (int)y0f;
            float w00 = (1.f - lx) * (1.f - ly);
            float w01 = lx * (1.f - ly);
            float w10 = (1.f - lx) * ly;
            float w11 = lx * ly;
            bool vx0 = (unsigned)x0       < (unsigned)IMW;
            bool vx1 = (unsigned)(x0 + 1) < (unsigned)IMW;
            bool vy0 = (unsigned)y0       < (unsigned)IMH;
            bool vy1 = (unsigned)(y0 + 1) < (unsigned)IMH;
            int cx0 = min(max(x0, 0), IMW - 1), cx1 = min(max(x0 + 1, 0), IMW - 1);
            int cy0 = min(max(y0, 0), IMH - 1), cy1 = min(max(y0 + 1, 0), IMH - 1);
            float c00 = (vx0 && vy0) ? a * w00 : 0.f;
            float c01 = (vx1 && vy0) ? a * w01 : 0.f;
            float c10 = (vx0 && vy1) ? a * w10 : 0.f;
            float c11 = (vx1 && vy1) ? a * w11 : 0.f;
            int i00 = cy0 * IMW + cx0, i01 = cy0 * IMW + cx1;
            int i10 = cy1 * IMW + cx0, i11 = cy1 * IMW + cx1;
            #pragma unroll
            for (int e = 0; e < 8; ++e) {
                const float* vp = vbase + (size_t)e * HWSZ;
                acc[e] += c00 * vp[i00] + c01 * vp[i01] + c10 * vp[i10] + c11 * vp[i11];
            }
        }
    }

    float* op = out + ((size_t)b * 32 + head * 8) * HWSZ + q;
    #pragma unroll
    for (int e = 0; e < 8; ++e) op[(size_t)e * HWSZ] = acc[e];
}

// ---------------- concat [out2, srcframe[:,1]] ----------------
__global__ void build_tseq_kernel(const float* __restrict__ out2,
                                  const float* __restrict__ srcframe,
                                  float* __restrict__ tseq)
{
    int id = blockIdx.x * blockDim.x + threadIdx.x;
    if (id >= BB * 64 * HWSZ) return;
    int q = id % HWSZ;
    int c = (id / HWSZ) & 63;
    int b = id / (64 * HWSZ);
    float v;
    if (c < 32) v = out2[((size_t)b * 32 + c) * HWSZ + q];
    else        v = srcframe[(((size_t)b * 3 + 1) * 32 + (c - 32)) * HWSZ + q];
    tseq[((size_t)b * 64 + c) * HWSZ + q] = v;
}

// ---------------- final 1x1 conv + lrelu ----------------
__global__ void conv1x1_lrelu_kernel(const float* __restrict__ in,
                                     const float* __restrict__ Wt,
                                     const float* __restrict__ bias,
                                     float* __restrict__ out)
{
    __shared__ float s_w[32][32];
    __shared__ float s_b[32];
    int tid = threadIdx.x;
    for (int idx = tid; idx < 32 * 32; idx += 256)
        s_w[idx >> 5][idx & 31] = Wt[idx];
    if (tid < 32) s_b[tid] = bias[tid];
    __syncthreads();

    int id = blockIdx.x * 256 + tid;
    if (id >= BB * HWSZ) return;
    int b = id / HWSZ, q = id % HWSZ;

    float x[32];
    #pragma unroll
    for (int ci = 0; ci < 32; ++ci)
        x[ci] = in[((size_t)b * 32 + ci) * HWSZ + q];

    #pragma unroll 4
    for (int oc = 0; oc < 32; ++oc) {
        float s = s_b[oc];
        #pragma unroll
        for (int ci = 0; ci < 32; ++ci)
            s += x[ci] * s_w[oc][ci];
        out[((size_t)b * 32 + oc) * HWSZ + q] = lrelu(s);
    }
}

// ---------------- host launcher ----------------
extern "C" void kernel_launch(void* const* d_in, const int* in_sizes, int n_in,
                              void* d_out, int out_size)
{
    const float* frame   = (const float*)d_in[0];
    const float* srcfr   = (const float*)d_in[1];
    const float* flow_f  = (const float*)d_in[2];
    const float* flow_b  = (const float*)d_in[3];
    const float* W_qk = (const float*)d_in[4];   const float* b_qk = (const float*)d_in[5];
    const float* W_v  = (const float*)d_in[6];   const float* b_v  = (const float*)d_in[7];
    const float* W_vp = (const float*)d_in[8];   const float* b_vp = (const float*)d_in[9];
    const float* W_off= (const float*)d_in[10];  const float* b_off= (const float*)d_in[11];
    const float* W_aw = (const float*)d_in[12];  const float* b_aw = (const float*)d_in[13];
    const float* W_out= (const float*)d_in[14];  const float* b_out= (const float*)d_in[15];
    const float* W_ffd= (const float*)d_in[16];  const float* b_ffd= (const float*)d_in[17];
    const float* W_ff1= (const float*)d_in[18];  const float* b_ff1= (const float*)d_in[19];
    const float* W_ff2= (const float*)d_in[20];  const float* b_ff2= (const float*)d_in[21];
    const float* W_fu = (const float*)d_in[22];  const float* b_fu = (const float*)d_in[23];

    float *qkin, *qureys, *value, *val, *off, *aw, *attn, *out1, *out2, *tseq, *ff1, *out3;
    cudaGetSymbolAddress((void**)&qkin,   g_qkin);
    cudaGetSymbolAddress((void**)&qureys, g_qureys);
    cudaGetSymbolAddress((void**)&value,  g_value);
    cudaGetSymbolAddress((void**)&val,    g_val);
    cudaGetSymbolAddress((void**)&off,    g_off);
    cudaGetSymbolAddress((void**)&aw,     g_aw);
    cudaGetSymbolAddress((void**)&attn,   g_attn);
    cudaGetSymbolAddress((void**)&out1,   g_out1);
    cudaGetSymbolAddress((void**)&out2,   g_out2);
    cudaGetSymbolAddress((void**)&tseq,   g_tseq);
    cudaGetSymbolAddress((void**)&ff1,    g_ff1);
    cudaGetSymbolAddress((void**)&out3,   g_out3);

    // 1. qk_in
    build_qkin_kernel<<<(BB * HWSZ + 255) / 256, 256>>>(frame, flow_f, flow_b, qkin);

    // 2. qureys = lrelu(conv(qk_in, W_qk))      CIN=100 COUT=96
    conv3x3_pipe<100, 1, 1, false><<<dim3(8, 16, BB * 6), 256>>>(
        qkin, W_qk, b_qk, nullptr, 0, qureys, 96);

    // 3. value = conv(frame(96ch), W_v)         CIN=96 COUT=96
    conv3x3_pipe<96, 1, 0, false><<<dim3(8, 16, BB * 6), 256>>>(
        frame, W_v, b_v, nullptr, 0, value, 96);

    // 4. val = conv(value as 6 x 32ch, W_vp)    nimg=6 CIN=32 COUT=32
    conv3x3_pipe<32, 1, 0, false><<<dim3(8, 16, 6 * 2), 256>>>(
        value, W_vp, b_vp, nullptr, 0, val, 32);

    // 5. off = conv(qureys, W_off)              CIN=96 COUT=96
    conv3x3_pipe<96, 1, 0, false><<<dim3(8, 16, BB * 6), 256>>>(
        qureys, W_off, b_off, nullptr, 0, off, 96);

    // 6. aw = conv(qureys, W_aw)                CIN=96 COUT=48
    conv3x3_pipe<96, 1, 0, false><<<dim3(8, 16, BB * 3), 256>>>(
        qureys, W_aw, b_aw, nullptr, 0, aw, 48);

    // 7. deformable attention
    deform_attn_kernel<<<(BB * 4 * HWSZ + 255) / 256, 256>>>(val, off, aw, attn);

    // 8. out1 = conv(attn, W_out)
    conv3x3_pipe<32, 1, 0, false><<<dim3(8, 16, BB * 2), 256>>>(
        attn, W_out, b_out, nullptr, 0, out1, 32);

    // 9. out2 = conv(out1, W_ffd) + frame[:,1]
    conv3x3_pipe<32, 1, 0, true><<<dim3(8, 16, BB * 2), 256>>>(
        out1, W_ffd, b_ffd, frame + (size_t)32 * HWSZ, (size_t)3 * 32 * HWSZ, out2, 32);

    // 10. tseq = concat(out2, srcframe[:,1])
    build_tseq_kernel<<<(BB * 64 * HWSZ + 255) / 256, 256>>>(out2, srcfr, tseq);

    // 11. ff1 = lrelu(conv(tseq, W_ff1, pad=2, dil=2))   CIN=64 COUT=32
    conv3x3_pipe<64, 2, 1, false><<<dim3(8, 16, BB * 2), 256>>>(
        tseq, W_ff1, b_ff1, nullptr, 0, ff1, 32);

    // 12. out3 = conv(ff1, W_ff2) + out2
    conv3x3_pipe<32, 1, 0, true><<<dim3(8, 16, BB * 2), 256>>>(
        ff1, W_ff2, b_ff2, out2, (size_t)32 * HWSZ, out3, 32);

    // 13. out = lrelu(conv1x1(out3, W_fu))
    conv1x1_lrelu_kernel<<<(BB * HWSZ + 255) / 256, 256>>>(out3, W_fu, b_fu, (float*)d_out);
}

// round 7
// speedup vs baseline: 1.5798x; 1.1427x over previous
#include <cuda_runtime.h>
#include <cstdint>
#include <math.h>

constexpr int IMH = 256, IMW = 256;
constexpr int HWSZ = IMH * IMW;       // 65536
constexpr int BB = 2;

// ---------------- scratch (device globals; no runtime allocation) ----------------
__device__ float g_qkin  [(size_t)BB * 100 * HWSZ];
__device__ float g_qureys[(size_t)BB *  96 * HWSZ];
__device__ float g_value [(size_t)BB *  96 * HWSZ];
__device__ float g_val   [(size_t)BB *  96 * HWSZ];
__device__ float g_off   [(size_t)BB *  96 * HWSZ];
__device__ float g_aw    [(size_t)BB *  48 * HWSZ];
__device__ float g_attn  [(size_t)BB *  32 * HWSZ];
__device__ float g_out1  [(size_t)BB *  32 * HWSZ];
__device__ float g_out2  [(size_t)BB *  32 * HWSZ];
__device__ float g_tseq  [(size_t)BB *  64 * HWSZ];
__device__ float g_ff1   [(size_t)BB *  32 * HWSZ];
__device__ float g_out3  [(size_t)BB *  32 * HWSZ];

__device__ __forceinline__ float lrelu(float v) { return v >= 0.f ? v : 0.1f * v; }

// ---------------- packed f32x2 helpers (Blackwell FFMA2) ----------------
__device__ __forceinline__ void ffma2(unsigned long long& acc, unsigned long long x,
                                      unsigned long long w)
{
    asm("fma.rn.f32x2 %0, %1, %2, %0;" : "+l"(acc) : "l"(x), "l"(w));
}
__device__ __forceinline__ unsigned long long packf2(float lo, float hi)
{
    unsigned long long r;
    asm("mov.b64 %0, {%1, %2};" : "=l"(r) : "f"(lo), "f"(hi));
    return r;
}
__device__ __forceinline__ void unpackf2(unsigned long long v, float& lo, float& hi)
{
    asm("mov.b64 {%0, %1}, %2;" : "=f"(lo), "=f"(hi) : "l"(v));
}

// ---------------- kernel 1: build qk_in (flow warps + concat) ----------------
__device__ __forceinline__ void sample32(const float* __restrict__ img, float sx, float sy,
                                         float* __restrict__ dst, int q)
{
    float x0f = floorf(sx), y0f = floorf(sy);
    float lx = sx - x0f, ly = sy - y0f;
    int x0 = (int)x0f, y0 = (int)y0f;
    float w00 = (1.f - lx) * (1.f - ly);
    float w01 = lx * (1.f - ly);
    float w10 = (1.f - lx) * ly;
    float w11 = lx * ly;
    bool vx0 = (unsigned)x0       < (unsigned)IMW;
    bool vx1 = (unsigned)(x0 + 1) < (unsigned)IMW;
    bool vy0 = (unsigned)y0       < (unsigned)IMH;
    bool vy1 = (unsigned)(y0 + 1) < (unsigned)IMH;
    int cx0 = min(max(x0, 0), IMW - 1), cx1 = min(max(x0 + 1, 0), IMW - 1);
    int cy0 = min(max(y0, 0), IMH - 1), cy1 = min(max(y0 + 1, 0), IMH - 1);
    int i00 = cy0 * IMW + cx0, i01 = cy0 * IMW + cx1;
    int i10 = cy1 * IMW + cx0, i11 = cy1 * IMW + cx1;
    float m00 = (vx0 && vy0) ? w00 : 0.f;
    float m01 = (vx1 && vy0) ? w01 : 0.f;
    float m10 = (vx0 && vy1) ? w10 : 0.f;
    float m11 = (vx1 && vy1) ? w11 : 0.f;
    #pragma unroll 4
    for (int c = 0; c < 32; ++c) {
        const float* p = img + (size_t)c * HWSZ;
        dst[(size_t)c * HWSZ + q] = m00 * p[i00] + m01 * p[i01] + m10 * p[i10] + m11 * p[i11];
    }
}

__global__ void build_qkin_kernel(const float* __restrict__ frame,
                                  const float* __restrict__ flow_f,
                                  const float* __restrict__ flow_b,
                                  float* __restrict__ qkin)
{
    int id = blockIdx.x * blockDim.x + threadIdx.x;
    if (id >= BB * HWSZ) return;
    int b = id / HWSZ, q = id % HWSZ;
    int px = q & (IMW - 1), py = q >> 8;

    const float* fb = flow_b + (size_t)b * 2 * 2 * HWSZ;
    float fbx = fb[q], fby = fb[HWSZ + q];
    const float* ff = flow_f + (size_t)b * 2 * 2 * HWSZ + (size_t)2 * HWSZ;
    float ffx = ff[q], ffy = ff[HWSZ + q];

    float* dst = qkin + (size_t)b * 100 * HWSZ;
    sample32(frame + ((size_t)b * 3 + 0) * 32 * HWSZ, (float)px + fbx, (float)py + fby, dst, q);
    const float* f1 = frame + ((size_t)b * 3 + 1) * 32 * HWSZ;
    #pragma unroll 4
    for (int c = 0; c < 32; ++c)
        dst[(size_t)(32 + c) * HWSZ + q] = f1[(size_t)c * HWSZ + q];
    sample32(frame + ((size_t)b * 3 + 2) * 32 * HWSZ, (float)px + ffx, (float)py + ffy,
             dst + (size_t)64 * HWSZ, q);
    dst[(size_t)96 * HWSZ + q] = ffx;
    dst[(size_t)97 * HWSZ + q] = ffy;
    dst[(size_t)98 * HWSZ + q] = fbx;
    dst[(size_t)99 * HWSZ + q] = fby;
}

// ---------------- cp.async helpers ----------------
__device__ __forceinline__ void cpasync4(unsigned int dst, const float* src, bool ok)
{
    int sz = ok ? 4 : 0;
    asm volatile("cp.async.ca.shared.global [%0], [%1], 4, %2;\n"
                 :: "r"(dst), "l"(src), "r"(sz));
}
__device__ __forceinline__ void cpasync_commit() {
    asm volatile("cp.async.commit_group;\n" ::: "memory");
}
__device__ __forceinline__ void cpasync_wait0() {
    asm volatile("cp.async.wait_group 0;\n" ::: "memory");
}

// ---------------- pipelined tiled 3x3 conv, FFMA2, 4 pixel rows/thread ----------------
// tile: 32(x) x 32(y) output pixels, 16 oc per block.
// thread: 4 pixel rows (py, py+8, py+16, py+24) x 16 oc; acc = f32x2 over oc pairs.
// All gmem->smem via cp.async with per-thread offsets precomputed ONCE.
template<int CIN, int DIL, int ACT, bool RES>
__global__ void __launch_bounds__(256, 2) conv3x3_pipe(
    const float* __restrict__ in, const float* __restrict__ Wt,
    const float* __restrict__ bias, const float* __restrict__ res, size_t resStride,
    float* __restrict__ out, int COUT)
{
    constexpr int TX = 32, TY = 32, OCB = 16;
    constexpr int IW = TX + 2 * DIL, IH = TY + 2 * DIL;
    constexpr int NCH = CIN / 4;
    constexpr int TILE_ELEMS = 4 * IH * IW;
    constexpr int NPF = (TILE_ELEMS + 255) / 256;   // per-thread input prefetch slots
    constexpr int PADDED = NPF * 256;
    constexpr int WELEMS = 4 * 9 * OCB;             // 576
    constexpr int NWF = (WELEMS + 255) / 256;       // 3
    constexpr int WPAD = NWF * 256;

    __shared__ float s_in[2][PADDED];
    __shared__ __align__(16) float s_w[2][WPAD];    // flat [ci][k][oc]

    const int tid = threadIdx.x;
    const int px = tid & 31, py = tid >> 5;          // px 0..31, py 0..7
    const int x0 = blockIdx.x * TX, y0 = blockIdx.y * TY;
    const int ngrp = COUT >> 4;
    const int img = blockIdx.z / ngrp;
    const int ocBase = (blockIdx.z % ngrp) * OCB;
    const float* inImg = in + (size_t)img * CIN * HWSZ;

    // ---- precompute per-thread prefetch offsets (chunk-invariant) ----
    unsigned int offIn[NPF];
    #pragma unroll
    for (int j = 0; j < NPF; ++j) {
        int idx = tid + j * 256;
        unsigned int o = 0x80000000u;  // invalid -> zero-fill
        if (idx < TILE_ELEMS) {
            int ci  = idx / (IH * IW);
            int rem = idx % (IH * IW);
            int ly = rem / IW, lx = rem % IW;
            int gy = y0 - DIL + ly, gx = x0 - DIL + lx;
            if ((unsigned)gy < (unsigned)IMH && (unsigned)gx < (unsigned)IMW)
                o = (unsigned int)(ci * HWSZ + gy * IMW + gx);
        }
        offIn[j] = o;
    }
    unsigned int offW[NWF];
    #pragma unroll
    for (int j = 0; j < NWF; ++j) {
        int idx = tid + j * 256;
        int oc = idx & 15;
        int k  = (idx >> 4) % 9;
        int ci = (idx >> 4) / 9;
        offW[j] = (unsigned int)(((ocBase + oc) * CIN + ci) * 9 + k);
    }
    const unsigned int sInBase0 = (unsigned int)__cvta_generic_to_shared(&s_in[0][0]);
    const unsigned int sInBase1 = (unsigned int)__cvta_generic_to_shared(&s_in[1][0]);
    const unsigned int sWBase0  = (unsigned int)__cvta_generic_to_shared(&s_w[0][0]);
    const unsigned int sWBase1  = (unsigned int)__cvta_generic_to_shared(&s_w[1][0]);

    unsigned long long acc[4][8];
    #pragma unroll
    for (int m = 0; m < 4; ++m)
        #pragma unroll
        for (int j = 0; j < 8; ++j) acc[m][j] = 0ULL;

    // ---- prefetch chunk `cc` into buffer `b` ----
    auto prefetch = [&](int cc, int b) {
        const float* chunkPtr = inImg + (size_t)cc * 4 * HWSZ;
        unsigned int sIn = b ? sInBase1 : sInBase0;
        unsigned int sW  = b ? sWBase1  : sWBase0;
        #pragma unroll
        for (int j = 0; j < NPF; ++j) {
            unsigned int o = offIn[j];
            bool ok = (int)o >= 0;
            cpasync4(sIn + (unsigned)(tid + j * 256) * 4,
                     chunkPtr + (o & 0x7FFFFFFFu), ok);
        }
        const unsigned int wAdd = (unsigned int)(cc * 4) * 9u;
        #pragma unroll
        for (int j = 0; j < NWF; ++j) {
            int idx = tid + j * 256;
            bool ok = idx < WELEMS;
            cpasync4(sW + (unsigned)idx * 4,
                     Wt + (ok ? (offW[j] + wAdd) : 0u), ok);
        }
    };

    prefetch(0, 0);
    cpasync_commit();
    cpasync_wait0();
    __syncthreads();

    int buf = 0;
    #pragma unroll 1
    for (int cc = 0; cc < NCH; ++cc) {
        if (cc + 1 < NCH) prefetch(cc + 1, buf ^ 1);
        cpasync_commit();

        // ---- compute current chunk ----
        const float* sI = &s_in[buf][0];
        const float* sW = &s_w[buf][0];
        #pragma unroll
        for (int ci = 0; ci < 4; ++ci) {
            #pragma unroll
            for (int k = 0; k < 9; ++k) {
                const int ky = k / 3, kx = k % 3;
                unsigned long long xp[4];
                #pragma unroll
                for (int m = 0; m < 4; ++m) {
                    float xv = sI[(ci * IH + py + m * 8 + ky * DIL) * IW + px + kx * DIL];
                    xp[m] = packf2(xv, xv);
                }
                const ulonglong2* wp =
                    reinterpret_cast<const ulonglong2*>(&sW[(ci * 9 + k) * OCB]);
                #pragma unroll
                for (int o4 = 0; o4 < 4; ++o4) {
                    ulonglong2 w2 = wp[o4];
                    #pragma unroll
                    for (int m = 0; m < 4; ++m) {
                        ffma2(acc[m][o4 * 2 + 0], xp[m], w2.x);
                        ffma2(acc[m][o4 * 2 + 1], xp[m], w2.y);
                    }
                }
            }
        }

        cpasync_wait0();
        __syncthreads();
        buf ^= 1;
    }

    const int ox = x0 + px;
    const size_t outImg = (size_t)img * COUT * HWSZ;
    #pragma unroll
    for (int j = 0; j < 8; ++j) {
        float b0 = bias[ocBase + 2 * j];
        float b1 = bias[ocBase + 2 * j + 1];
        #pragma unroll
        for (int m = 0; m < 4; ++m) {
            int oy = y0 + py + m * 8;
            float v0, v1;
            unpackf2(acc[m][j], v0, v1);
            v0 += b0;
            v1 += b1;
            if (RES) {
                const float* rp = res + (size_t)img * resStride;
                v0 += rp[(size_t)(ocBase + 2 * j)     * HWSZ + oy * IMW + ox];
                v1 += rp[(size_t)(ocBase + 2 * j + 1) * HWSZ + oy * IMW + ox];
            }
            if (ACT) { v0 = lrelu(v0); v1 = lrelu(v1); }
            out[outImg + (size_t)(ocBase + 2 * j)     * HWSZ + oy * IMW + ox] = v0;
            out[outImg + (size_t)(ocBase + 2 * j + 1) * HWSZ + oy * IMW + ox] = v1;
        }
    }
}

// ---------------- deformable attention ----------------
__global__ void deform_attn_kernel(const float* __restrict__ val,
                                   const float* __restrict__ off,
                                   const float* __restrict__ awl,
                                   float* __restrict__ out)
{
    int id = blockIdx.x * blockDim.x + threadIdx.x;
    if (id >= BB * 4 * HWSZ) return;
    int q = id % HWSZ;
    int head = (id / HWSZ) & 3;
    int b = id / (4 * HWSZ);
    int px = q & (IMW - 1), py = q >> 8;

    const float* awp = awl + ((size_t)b * 48 + head * 12) * HWSZ + q;
    float lg[12];
    float mx = -1e30f;
    #pragma unroll
    for (int i = 0; i < 12; ++i) { lg[i] = awp[(size_t)i * HWSZ]; mx = fmaxf(mx, lg[i]); }
    float s = 0.f;
    #pragma unroll
    for (int i = 0; i < 12; ++i) { lg[i] = expf(lg[i] - mx); s += lg[i]; }
    float inv = 1.f / s;

    float acc[8];
    #pragma unroll
    for (int e = 0; e < 8; ++e) acc[e] = 0.f;

    const float* offp = off + ((size_t)b * 96 + head * 24) * HWSZ + q;

    for (int l = 0; l < 3; ++l) {
        const float* vbase = val + (((size_t)b * 3 + l) * 32 + head * 8) * HWSZ;
        #pragma unroll
        for (int p = 0; p < 4; ++p) {
            int ch = (l * 4 + p) * 2;
            float sx = (float)px + offp[(size_t)ch * HWSZ];
            float sy = (float)py + offp[(size_t)(ch + 1) * HWSZ];
            float a = lg[l * 4 + p] * inv;

            float x0f = floorf(sx), y0f = floorf(sy);
            float lx = sx - x0f, ly = sy - y0f;
            int x0 = (int)x0f, y0 = (int)y0f;
            float w00 = (1.f - lx) * (1.f - ly);
            float w01 = lx * (1.f - ly);
            float w10 = (1.f - lx) * ly;
            float w11 = lx * ly;
            bool vx0 = (unsigned)x0       < (unsigned)IMW;
            bool vx1 = (unsigned)(x0 + 1) < (unsigned)IMW;
            bool vy0 = (unsigned)y0       < (unsigned)IMH;
            bool vy1 = (unsigned)(y0 + 1) < (unsigned)IMH;
            int cx0 = min(max(x0, 0), IMW - 1), cx1 = min(max(x0 + 1, 0), IMW - 1);
            int cy0 = min(max(y0, 0), IMH - 1), cy1 = min(max(y0 + 1, 0), IMH - 1);
            float c00 = (vx0 && vy0) ? a * w00 : 0.f;
            float c01 = (vx1 && vy0) ? a * w01 : 0.f;
            float c10 = (vx0 && vy1) ? a * w10 : 0.f;
            float c11 = (vx1 && vy1) ? a * w11 : 0.f;
            int i00 = cy0 * IMW + cx0, i01 = cy0 * IMW + cx1;
            int i10 = cy1 * IMW + cx0, i11 = cy1 * IMW + cx1;
            #pragma unroll
            for (int e = 0; e < 8; ++e) {
                const float* vp = vbase + (size_t)e * HWSZ;
                acc[e] += c00 * vp[i00] + c01 * vp[i01] + c10 * vp[i10] + c11 * vp[i11];
            }
        }
    }

    float* op = out + ((size_t)b * 32 + head * 8) * HWSZ + q;
    #pragma unroll
    for (int e = 0; e < 8; ++e) op[(size_t)e * HWSZ] = acc[e];
}

// ---------------- concat [out2, srcframe[:,1]] ----------------
__global__ void build_tseq_kernel(const float* __restrict__ out2,
                                  const float* __restrict__ srcframe,
                                  float* __restrict__ tseq)
{
    int id = blockIdx.x * blockDim.x + threadIdx.x;
    if (id >= BB * 64 * HWSZ) return;
    int q = id % HWSZ;
    int c = (id / HWSZ) & 63;
    int b = id / (64 * HWSZ);
    float v;
    if (c < 32) v = out2[((size_t)b * 32 + c) * HWSZ + q];
    else        v = srcframe[(((size_t)b * 3 + 1) * 32 + (c - 32)) * HWSZ + q];
    tseq[((size_t)b * 64 + c) * HWSZ + q] = v;
}

// ---------------- final 1x1 conv + lrelu ----------------
__global__ void conv1x1_lrelu_kernel(const float* __restrict__ in,
                                     const float* __restrict__ Wt,
                                     const float* __restrict__ bias,
                                     float* __restrict__ out)
{
    __shared__ float s_w[32][32];
    __shared__ float s_b[32];
    int tid = threadIdx.x;
    for (int idx = tid; idx < 32 * 32; idx += 256)
        s_w[idx >> 5][idx & 31] = Wt[idx];
    if (tid < 32) s_b[tid] = bias[tid];
    __syncthreads();

    int id = blockIdx.x * 256 + tid;
    if (id >= BB * HWSZ) return;
    int b = id / HWSZ, q = id % HWSZ;

    float x[32];
    #pragma unroll
    for (int ci = 0; ci < 32; ++ci)
        x[ci] = in[((size_t)b * 32 + ci) * HWSZ + q];

    #pragma unroll 4
    for (int oc = 0; oc < 32; ++oc) {
        float s = s_b[oc];
        #pragma unroll
        for (int ci = 0; ci < 32; ++ci)
            s += x[ci] * s_w[oc][ci];
        out[((size_t)b * 32 + oc) * HWSZ + q] = lrelu(s);
    }
}

// ---------------- host launcher ----------------
extern "C" void kernel_launch(void* const* d_in, const int* in_sizes, int n_in,
                              void* d_out, int out_size)
{
    const float* frame   = (const float*)d_in[0];
    const float* srcfr   = (const float*)d_in[1];
    const float* flow_f  = (const float*)d_in[2];
    const float* flow_b  = (const float*)d_in[3];
    const float* W_qk = (const float*)d_in[4];   const float* b_qk = (const float*)d_in[5];
    const float* W_v  = (const float*)d_in[6];   const float* b_v  = (const float*)d_in[7];
    const float* W_vp = (const float*)d_in[8];   const float* b_vp = (const float*)d_in[9];
    const float* W_off= (const float*)d_in[10];  const float* b_off= (const float*)d_in[11];
    const float* W_aw = (const float*)d_in[12];  const float* b_aw = (const float*)d_in[13];
    const float* W_out= (const float*)d_in[14];  const float* b_out= (const float*)d_in[15];
    const float* W_ffd= (const float*)d_in[16];  const float* b_ffd= (const float*)d_in[17];
    const float* W_ff1= (const float*)d_in[18];  const float* b_ff1= (const float*)d_in[19];
    const float* W_ff2= (const float*)d_in[20];  const float* b_ff2= (const float*)d_in[21];
    const float* W_fu = (const float*)d_in[22];  const float* b_fu = (const float*)d_in[23];

    float *qkin, *qureys, *value, *val, *off, *aw, *attn, *out1, *out2, *tseq, *ff1, *out3;
    cudaGetSymbolAddress((void**)&qkin,   g_qkin);
    cudaGetSymbolAddress((void**)&qureys, g_qureys);
    cudaGetSymbolAddress((void**)&value,  g_value);
    cudaGetSymbolAddress((void**)&val,    g_val);
    cudaGetSymbolAddress((void**)&off,    g_off);
    cudaGetSymbolAddress((void**)&aw,     g_aw);
    cudaGetSymbolAddress((void**)&attn,   g_attn);
    cudaGetSymbolAddress((void**)&out1,   g_out1);
    cudaGetSymbolAddress((void**)&out2,   g_out2);
    cudaGetSymbolAddress((void**)&tseq,   g_tseq);
    cudaGetSymbolAddress((void**)&ff1,    g_ff1);
    cudaGetSymbolAddress((void**)&out3,   g_out3);

    // tile grid: 32x32 px per block
    const dim3 blk(256);

    // 1. qk_in
    build_qkin_kernel<<<(BB * HWSZ + 255) / 256, 256>>>(frame, flow_f, flow_b, qkin);

    // 2. qureys = lrelu(conv(qk_in, W_qk))      CIN=100 COUT=96
    conv3x3_pipe<100, 1, 1, false><<<dim3(8, 8, BB * 6), blk>>>(
        qkin, W_qk, b_qk, nullptr, 0, qureys, 96);

    // 3. value = conv(frame(96ch), W_v)         CIN=96 COUT=96
    conv3x3_pipe<96, 1, 0, false><<<dim3(8, 8, BB * 6), blk>>>(
        frame, W_v, b_v, nullptr, 0, value, 96);

    // 4. val = conv(value as 6 x 32ch, W_vp)    nimg=6 CIN=32 COUT=32
    conv3x3_pipe<32, 1, 0, false><<<dim3(8, 8, 6 * 2), blk>>>(
        value, W_vp, b_vp, nullptr, 0, val, 32);

    // 5. off = conv(qureys, W_off)              CIN=96 COUT=96
    conv3x3_pipe<96, 1, 0, false><<<dim3(8, 8, BB * 6), blk>>>(
        qureys, W_off, b_off, nullptr, 0, off, 96);

    // 6. aw = conv(qureys, W_aw)                CIN=96 COUT=48
    conv3x3_pipe<96, 1, 0, false><<<dim3(8, 8, BB * 3), blk>>>(
        qureys, W_aw, b_aw, nullptr, 0, aw, 48);

    // 7. deformable attention
    deform_attn_kernel<<<(BB * 4 * HWSZ + 255) / 256, 256>>>(val, off, aw, attn);

    // 8. out1 = conv(attn, W_out)
    conv3x3_pipe<32, 1, 0, false><<<dim3(8, 8, BB * 2), blk>>>(
        attn, W_out, b_out, nullptr, 0, out1, 32);

    // 9. out2 = conv(out1, W_ffd) + frame[:,1]
    conv3x3_pipe<32, 1, 0, true><<<dim3(8, 8, BB * 2), blk>>>(
        out1, W_ffd, b_ffd, frame + (size_t)32 * HWSZ, (size_t)3 * 32 * HWSZ, out2, 32);

    // 10. tseq = concat(out2, srcframe[:,1])
    build_tseq_kernel<<<(BB * 64 * HWSZ + 255) / 256, 256>>>(out2, srcfr, tseq);

    // 11. ff1 = lrelu(conv(tseq, W_ff1, pad=2, dil=2))   CIN=64 COUT=32
    conv3x3_pipe<64, 2, 1, false><<<dim3(8, 8, BB * 2), blk>>>(
        tseq, W_ff1, b_ff1, nullptr, 0, ff1, 32);

    // 12. out3 = conv(ff1, W_ff2) + out2
    conv3x3_pipe<32, 1, 0, true><<<dim3(8, 8, BB * 2), blk>>>(
        ff1, W_ff2, b_ff2, out2, (size_t)32 * HWSZ, out3, 32);

    // 13. out = lrelu(conv1x1(out3, W_fu))
    conv1x1_lrelu_kernel<<<(BB * HWSZ + 255) / 256, 256>>>(out3, W_fu, b_fu, (float*)d_out);
}

// round 12
// speedup vs baseline: 1.6792x; 1.0629x over previous
#include <cuda_runtime.h>
#include <cstdint>
#include <math.h>

constexpr int IMH = 256, IMW = 256;
constexpr int HWSZ = IMH * IMW;       // 65536
constexpr int BB = 2;

// ---------------- scratch (device globals; no runtime allocation) ----------------
__device__ float g_qkin  [(size_t)BB * 100 * HWSZ];
__device__ float g_qureys[(size_t)BB *  96 * HWSZ];
__device__ float g_value [(size_t)BB *  96 * HWSZ];
__device__ float g_val   [(size_t)BB *  96 * HWSZ];
__device__ float g_off   [(size_t)BB *  96 * HWSZ];
__device__ float g_aw    [(size_t)BB *  48 * HWSZ];
__device__ float g_attn  [(size_t)BB *  32 * HWSZ];
__device__ float g_out1  [(size_t)BB *  32 * HWSZ];
__device__ float g_out2  [(size_t)BB *  32 * HWSZ];
__device__ float g_tseq  [(size_t)BB *  64 * HWSZ];
__device__ float g_ff1   [(size_t)BB *  32 * HWSZ];
__device__ float g_out3  [(size_t)BB *  32 * HWSZ];

__device__ __forceinline__ float lrelu(float v) { return v >= 0.f ? v : 0.1f * v; }

// ---------------- packed f32x2 helpers (Blackwell FFMA2) ----------------
__device__ __forceinline__ void ffma2(unsigned long long& acc, unsigned long long x,
                                      unsigned long long w)
{
    asm("fma.rn.f32x2 %0, %1, %2, %0;" : "+l"(acc) : "l"(x), "l"(w));
}
__device__ __forceinline__ unsigned long long packf2(float lo, float hi)
{
    unsigned long long r;
    asm("mov.b64 %0, {%1, %2};" : "=l"(r) : "f"(lo), "f"(hi));
    return r;
}
__device__ __forceinline__ void unpackf2(unsigned long long v, float& lo, float& hi)
{
    asm("mov.b64 {%0, %1}, %2;" : "=f"(lo), "=f"(hi) : "l"(v));
}

// ---------------- kernel 1: build qk_in (flow warps + concat) ----------------
__device__ __forceinline__ void sample32(const float* __restrict__ img, float sx, float sy,
                                         float* __restrict__ dst, int q)
{
    float x0f = floorf(sx), y0f = floorf(sy);
    float lx = sx - x0f, ly = sy - y0f;
    int x0 = (int)x0f, y0 = (int)y0f;
    float w00 = (1.f - lx) * (1.f - ly);
    float w01 = lx * (1.f - ly);
    float w10 = (1.f - lx) * ly;
    float w11 = lx * ly;
    bool vx0 = (unsigned)x0       < (unsigned)IMW;
    bool vx1 = (unsigned)(x0 + 1) < (unsigned)IMW;
    bool vy0 = (unsigned)y0       < (unsigned)IMH;
    bool vy1 = (unsigned)(y0 + 1) < (unsigned)IMH;
    int cx0 = min(max(x0, 0), IMW - 1), cx1 = min(max(x0 + 1, 0), IMW - 1);
    int cy0 = min(max(y0, 0), IMH - 1), cy1 = min(max(y0 + 1, 0), IMH - 1);
    int i00 = cy0 * IMW + cx0, i01 = cy0 * IMW + cx1;
    int i10 = cy1 * IMW + cx0, i11 = cy1 * IMW + cx1;
    float m00 = (vx0 && vy0) ? w00 : 0.f;
    float m01 = (vx1 && vy0) ? w01 : 0.f;
    float m10 = (vx0 && vy1) ? w10 : 0.f;
    float m11 = (vx1 && vy1) ? w11 : 0.f;
    #pragma unroll 4
    for (int c = 0; c < 32; ++c) {
        const float* p = img + (size_t)c * HWSZ;
        dst[(size_t)c * HWSZ + q] = m00 * p[i00] + m01 * p[i01] + m10 * p[i10] + m11 * p[i11];
    }
}

__global__ void build_qkin_kernel(const float* __restrict__ frame,
                                  const float* __restrict__ flow_f,
                                  const float* __restrict__ flow_b,
                                  float* __restrict__ qkin)
{
    int id = blockIdx.x * blockDim.x + threadIdx.x;
    if (id >= BB * HWSZ) return;
    int b = id / HWSZ, q = id % HWSZ;
    int px = q & (IMW - 1), py = q >> 8;

    const float* fb = flow_b + (size_t)b * 2 * 2 * HWSZ;
    float fbx = fb[q], fby = fb[HWSZ + q];
    const float* ff = flow_f + (size_t)b * 2 * 2 * HWSZ + (size_t)2 * HWSZ;
    float ffx = ff[q], ffy = ff[HWSZ + q];

    float* dst = qkin + (size_t)b * 100 * HWSZ;
    sample32(frame + ((size_t)b * 3 + 0) * 32 * HWSZ, (float)px + fbx, (float)py + fby, dst, q);
    const float* f1 = frame + ((size_t)b * 3 + 1) * 32 * HWSZ;
    #pragma unroll 4
    for (int c = 0; c < 32; ++c)
        dst[(size_t)(32 + c) * HWSZ + q] = f1[(size_t)c * HWSZ + q];
    sample32(frame + ((size_t)b * 3 + 2) * 32 * HWSZ, (float)px + ffx, (float)py + ffy,
             dst + (size_t)64 * HWSZ, q);
    dst[(size_t)96 * HWSZ + q] = ffx;
    dst[(size_t)97 * HWSZ + q] = ffy;
    dst[(size_t)98 * HWSZ + q] = fbx;
    dst[(size_t)99 * HWSZ + q] = fby;
}

// ---------------- cp.async helpers ----------------
__device__ __forceinline__ void cpasync4(unsigned int dst, const float* src, bool ok)
{
    int sz = ok ? 4 : 0;
    asm volatile("cp.async.ca.shared.global [%0], [%1], 4, %2;\n"
                 :: "r"(dst), "l"(src), "r"(sz));
}
__device__ __forceinline__ void cpasync_commit() {
    asm volatile("cp.async.commit_group;\n" ::: "memory");
}
__device__ __forceinline__ void cpasync_wait0() {
    asm volatile("cp.async.wait_group 0;\n" ::: "memory");
}

// ---------------- conv geometry (host+device shared formulas) ----------------
__host__ __device__ constexpr int cdiv_(int a, int b) { return (a + b - 1) / b; }
__host__ __device__ constexpr int convIW(int DIL)   { return 32 + 2 * DIL; }
__host__ __device__ constexpr int convPPAD(int DIL) { return cdiv_(convIW(DIL) * convIW(DIL), 256) * 256; }
__host__ __device__ constexpr int convWPAD(int CH)  { return cdiv_(CH * 9 * 16, 256) * 256; }
__host__ __device__ constexpr int convSmemBytes(int CH, int DIL)
{
    return (2 * CH * convPPAD(DIL) + 2 * convWPAD(CH)) * 4;
}

// ---------------- pipelined tiled 3x3 conv, FFMA2, 4 pixel rows/thread ----------------
// tile: 32x32 output pixels, 16 oc per block; thread: 4 rows x 16 oc (f32x2 oc-pairs).
// Channel-major prefetch: per-plane geometry offsets precomputed once (5-6 regs).
// CH input channels per pipeline stage (zero-filled past cin). Runtime cin/COUT.
// Optional second segment (Wt2/out2) merges an independent conv into the same grid.
template<int CH, int DIL, int ACT, bool RES>
__global__ void __launch_bounds__(256, 2) conv3x3_pipe(
    const float* __restrict__ in, const float* __restrict__ Wt,
    const float* __restrict__ bias, const float* __restrict__ res, size_t resStride,
    float* __restrict__ out, int cin, int COUT,
    const float* __restrict__ Wt2, const float* __restrict__ bias2,
    float* __restrict__ out2, int COUT2, int zSplit)
{
    constexpr int OCB = 16;
    constexpr int IW = convIW(DIL), IH = IW;
    constexpr int PLANE = IH * IW;
    constexpr int NPF = cdiv_(PLANE, 256);
    constexpr int PPAD = NPF * 256;
    constexpr int WELEMS = CH * 9 * OCB;
    constexpr int NWF = cdiv_(WELEMS, 256);
    constexpr int WPAD = NWF * 256;

    extern __shared__ float smem[];
    float* s_in = smem;                       // [2][CH*PPAD]
    float* s_wp = smem + 2 * CH * PPAD;       // [2][WPAD]

    const int tid = threadIdx.x;
    const int px = tid & 31, py = tid >> 5;   // px 0..31, py 0..7
    const int x0 = blockIdx.x * 32, y0 = blockIdx.y * 32;

    // segment resolution (merged launches)
    int z = blockIdx.z;
    const float* wPtr = Wt;  const float* bPtr = bias;  float* oPtr = out;  int cout = COUT;
    if (Wt2 != nullptr && z >= zSplit) {
        wPtr = Wt2; bPtr = bias2; oPtr = out2; cout = COUT2; z -= zSplit;
    }
    const int ngrp = cout >> 4;
    const int img = z / ngrp;
    const int ocBase = (z % ngrp) * OCB;
    const float* inImg = in + (size_t)img * cin * HWSZ;
    const int NCH = (cin + CH - 1) / CH;

    // ---- per-plane geometry offsets (chunk & channel invariant) ----
    unsigned int offGeo[NPF];
    #pragma unroll
    for (int j = 0; j < NPF; ++j) {
        int idx = tid + j * 256;
        unsigned int o = 0x80000000u;
        if (idx < PLANE) {
            int ly = idx / IW, lx = idx % IW;
            int gy = y0 - DIL + ly, gx = x0 - DIL + lx;
            if ((unsigned)gy < (unsigned)IMH && (unsigned)gx < (unsigned)IMW)
                o = (unsigned int)(gy * IMW + gx);
        }
        offGeo[j] = o;
    }
    // ---- weight slot offsets ----
    unsigned int offW[NWF];
    int ciSlotW[NWF];
    #pragma unroll
    for (int j = 0; j < NWF; ++j) {
        int idx = tid + j * 256;
        if (idx < WELEMS) {
            int oc = idx & 15;
            int k  = (idx >> 4) % 9;
            int ci = (idx >> 4) / 9;
            offW[j] = (unsigned int)(((ocBase + oc) * cin + ci) * 9 + k);
            ciSlotW[j] = ci;
        } else { offW[j] = 0; ciSlotW[j] = 0x7FFFFFF; }
    }
    const unsigned int sBase = (unsigned int)__cvta_generic_to_shared(smem);

    unsigned long long acc[4][8];
    #pragma unroll
    for (int m = 0; m < 4; ++m)
        #pragma unroll
        for (int j = 0; j < 8; ++j) acc[m][j] = 0ULL;

    auto prefetch = [&](int cc, int b) {
        const float* base = inImg + (size_t)cc * CH * HWSZ;
        unsigned int sIn = sBase + (unsigned)(b * CH * PPAD) * 4;
        unsigned int sW  = sBase + (unsigned)((2 * CH * PPAD) + b * WPAD) * 4;
        const int chLim = cin - cc * CH;   // valid channels this chunk
        #pragma unroll
        for (int ci = 0; ci < CH; ++ci) {
            bool chOk = ci < chLim;
            const float* cp = base + (size_t)ci * HWSZ;
            #pragma unroll
            for (int j = 0; j < NPF; ++j) {
                unsigned int o = offGeo[j];
                bool ok = chOk && !(o & 0x80000000u);
                cpasync4(sIn + (unsigned)(ci * PPAD + tid + j * 256) * 4,
                         cp + (o & 0x7FFFFFFFu), ok);
            }
        }
        const unsigned int wAdd = (unsigned int)(cc * CH) * 9u;
        #pragma unroll
        for (int j = 0; j < NWF; ++j) {
            bool ok = ciSlotW[j] < chLim;
            cpasync4(sW + (unsigned)(tid + j * 256) * 4,
                     wPtr + (ok ? (offW[j] + wAdd) : 0u), ok);
        }
    };

    prefetch(0, 0);
    cpasync_commit();
    cpasync_wait0();
    __syncthreads();

    int buf = 0;
    #pragma unroll 1
    for (int cc = 0; cc < NCH; ++cc) {
        if (cc + 1 < NCH) prefetch(cc + 1, buf ^ 1);
        cpasync_commit();

        const float* sI = s_in + buf * CH * PPAD;
        const float* sW = s_wp + buf * WPAD;
        #pragma unroll 1
        for (int ci = 0; ci < CH; ++ci) {
            const float* sIc = sI + ci * PPAD;
            const float* sWc = sW + ci * 9 * OCB;
            #pragma unroll
            for (int k = 0; k < 9; ++k) {
                const int ky = k / 3, kx = k % 3;
                unsigned long long xp[4];
                #pragma unroll
                for (int m = 0; m < 4; ++m) {
                    float xv = sIc[(py + m * 8 + ky * DIL) * IW + px + kx * DIL];
                    xp[m] = packf2(xv, xv);
                }
                const ulonglong2* wp = reinterpret_cast<const ulonglong2*>(sWc + k * OCB);
                #pragma unroll
                for (int o4 = 0; o4 < 4; ++o4) {
                    ulonglong2 w2 = wp[o4];
                    #pragma unroll
                    for (int m = 0; m < 4; ++m) {
                        ffma2(acc[m][o4 * 2 + 0], xp[m], w2.x);
                        ffma2(acc[m][o4 * 2 + 1], xp[m], w2.y);
                    }
                }
            }
        }

        cpasync_wait0();
        __syncthreads();
        buf ^= 1;
    }

    const int ox = x0 + px;
    const size_t outImg = (size_t)img * cout * HWSZ;
    #pragma unroll
    for (int j = 0; j < 8; ++j) {
        float b0 = bPtr[ocBase + 2 * j];
        float b1 = bPtr[ocBase + 2 * j + 1];
        #pragma unroll
        for (int m = 0; m < 4; ++m) {
            int oy = y0 + py + m * 8;
            float v0, v1;
            unpackf2(acc[m][j], v0, v1);
            v0 += b0;
            v1 += b1;
            if (RES) {
                const float* rp = res + (size_t)img * resStride;
                v0 += rp[(size_t)(ocBase + 2 * j)     * HWSZ + oy * IMW + ox];
                v1 += rp[(size_t)(ocBase + 2 * j + 1) * HWSZ + oy * IMW + ox];
            }
            if (ACT) { v0 = lrelu(v0); v1 = lrelu(v1); }
            oPtr[outImg + (size_t)(ocBase + 2 * j)     * HWSZ + oy * IMW + ox] = v0;
            oPtr[outImg + (size_t)(ocBase + 2 * j + 1) * HWSZ + oy * IMW + ox] = v1;
        }
    }
}

// ---------------- deformable attention ----------------
__global__ void deform_attn_kernel(const float* __restrict__ val,
                                   const float* __restrict__ off,
                                   const float* __restrict__ awl,
                                   float* __restrict__ out)
{
    int id = blockIdx.x * blockDim.x + threadIdx.x;
    if (id >= BB * 4 * HWSZ) return;
    int q = id % HWSZ;
    int head = (id / HWSZ) & 3;
    int b = id / (4 * HWSZ);
    int px = q & (IMW - 1), py = q >> 8;

    const float* awp = awl + ((size_t)b * 48 + head * 12) * HWSZ + q;
    float lg[12];
    float mx = -1e30f;
    #pragma unroll
    for (int i = 0; i < 12; ++i) { lg[i] = awp[(size_t)i * HWSZ]; mx = fmaxf(mx, lg[i]); }
    float s = 0.f;
    #pragma unroll
    for (int i = 0; i < 12; ++i) { lg[i] = expf(lg[i] - mx); s += lg[i]; }
    float inv = 1.f / s;

    float acc[8];
    #pragma unroll
    for (int e = 0; e < 8; ++e) acc[e] = 0.f;

    const float* offp = off + ((size_t)b * 96 + head * 24) * HWSZ + q;

    for (int l = 0; l < 3; ++l) {
        const float* vbase = val + (((size_t)b * 3 + l) * 32 + head * 8) * HWSZ;
        #pragma unroll
        for (int p = 0; p < 4; ++p) {
            int ch = (l * 4 + p) * 2;
            float sx = (float)px + offp[(size_t)ch * HWSZ];
            float sy = (float)py + offp[(size_t)(ch + 1) * HWSZ];
            float a = lg[l * 4 + p] * inv;

            float x0f = floorf(sx), y0f = floorf(sy);
            float lx = sx - x0f, ly = sy - y0f;
            int x0 = (int)x0f, y0 = (int)y0f;
            float w00 = (1.f - lx) * (1.f - ly);
            float w01 = lx * (1.f - ly);
            float w10 = (1.f - lx) * ly;
            float w11 = lx * ly;
            bool vx0 = (unsigned)x0       < (unsigned)IMW;
            bool vx1 = (unsigned)(x0 + 1) < (unsigned)IMW;
            bool vy0 = (unsigned)y0       < (unsigned)IMH;
            bool vy1 = (unsigned)(y0 + 1) < (unsigned)IMH;
            int cx0 = min(max(x0, 0), IMW - 1), cx1 = min(max(x0 + 1, 0), IMW - 1);
            int cy0 = min(max(y0, 0), IMH - 1), cy1 = min(max(y0 + 1, 0), IMH - 1);
            float c00 = (vx0 && vy0) ? a * w00 : 0.f;
            float c01 = (vx1 && vy0) ? a * w01 : 0.f;
            float c10 = (vx0 && vy1) ? a * w10 : 0.f;
            float c11 = (vx1 && vy1) ? a * w11 : 0.f;
            int i00 = cy0 * IMW + cx0, i01 = cy0 * IMW + cx1;
            int i10 = cy1 * IMW + cx0, i11 = cy1 * IMW + cx1;
            #pragma unroll
            for (int e = 0; e < 8; ++e) {
                const float* vp = vbase + (size_t)e * HWSZ;
                acc[e] += c00 * vp[i00] + c01 * vp[i01] + c10 * vp[i10] + c11 * vp[i11];
            }
        }
    }

    float* op = out + ((size_t)b * 32 + head * 8) * HWSZ + q;
    #pragma unroll
    for (int e = 0; e < 8; ++e) op[(size_t)e * HWSZ] = acc[e];
}

// ---------------- concat [out2, srcframe[:,1]] ----------------
__global__ void build_tseq_kernel(const float* __restrict__ out2,
                                  const float* __restrict__ srcframe,
                                  float* __restrict__ tseq)
{
    int id = blockIdx.x * blockDim.x + threadIdx.x;
    if (id >= BB * 64 * HWSZ) return;
    int q = id % HWSZ;
    int c = (id / HWSZ) & 63;
    int b = id / (64 * HWSZ);
    float v;
    if (c < 32) v = out2[((size_t)b * 32 + c) * HWSZ + q];
    else        v = srcframe[(((size_t)b * 3 + 1) * 32 + (c - 32)) * HWSZ + q];
    tseq[((size_t)b * 64 + c) * HWSZ + q] = v;
}

// ---------------- final 1x1 conv + lrelu ----------------
__global__ void conv1x1_lrelu_kernel(const float* __restrict__ in,
                                     const float* __restrict__ Wt,
                                     const float* __restrict__ bias,
                                     float* __restrict__ out)
{
    __shared__ float s_w[32][32];
    __shared__ float s_b[32];
    int tid = threadIdx.x;
    for (int idx = tid; idx < 32 * 32; idx += 256)
        s_w[idx >> 5][idx & 31] = Wt[idx];
    if (tid < 32) s_b[tid] = bias[tid];
    __syncthreads();

    int id = blockIdx.x * 256 + tid;
    if (id >= BB * HWSZ) return;
    int b = id / HWSZ, q = id % HWSZ;

    float x[32];
    #pragma unroll
    for (int ci = 0; ci < 32; ++ci)
        x[ci] = in[((size_t)b * 32 + ci) * HWSZ + q];

    #pragma unroll 4
    for (int oc = 0; oc < 32; ++oc) {
        float s = s_b[oc];
        #pragma unroll
        for (int ci = 0; ci < 32; ++ci)
            s += x[ci] * s_w[oc][ci];
        out[((size_t)b * 32 + oc) * HWSZ + q] = lrelu(s);
    }
}

// ---------------- host launcher ----------------
extern "C" void kernel_launch(void* const* d_in, const int* in_sizes, int n_in,
                              void* d_out, int out_size)
{
    const float* frame   = (const float*)d_in[0];
    const float* srcfr   = (const float*)d_in[1];
    const float* flow_f  = (const float*)d_in[2];
    const float* flow_b  = (const float*)d_in[3];
    const float* W_qk = (const float*)d_in[4];   const float* b_qk = (const float*)d_in[5];
    const float* W_v  = (const float*)d_in[6];   const float* b_v  = (const float*)d_in[7];
    const float* W_vp = (const float*)d_in[8];   const float* b_vp = (const float*)d_in[9];
    const float* W_off= (const float*)d_in[10];  const float* b_off= (const float*)d_in[11];
    const float* W_aw = (const float*)d_in[12];  const float* b_aw = (const float*)d_in[13];
    const float* W_out= (const float*)d_in[14];  const float* b_out= (const float*)d_in[15];
    const float* W_ffd= (const float*)d_in[16];  const float* b_ffd= (const float*)d_in[17];
    const float* W_ff1= (const float*)d_in[18];  const float* b_ff1= (const float*)d_in[19];
    const float* W_ff2= (const float*)d_in[20];  const float* b_ff2= (const float*)d_in[21];
    const float* W_fu = (const float*)d_in[22];  const float* b_fu = (const float*)d_in[23];

    float *qkin, *qureys, *value, *val, *off, *aw, *attn, *out1, *out2, *tseq, *ff1, *out3;
    cudaGetSymbolAddress((void**)&qkin,   g_qkin);
    cudaGetSymbolAddress((void**)&qureys, g_qureys);
    cudaGetSymbolAddress((void**)&value,  g_value);
    cudaGetSymbolAddress((void**)&val,    g_val);
    cudaGetSymbolAddress((void**)&off,    g_off);
    cudaGetSymbolAddress((void**)&aw,     g_aw);
    cudaGetSymbolAddress((void**)&attn,   g_attn);
    cudaGetSymbolAddress((void**)&out1,   g_out1);
    cudaGetSymbolAddress((void**)&out2,   g_out2);
    cudaGetSymbolAddress((void**)&tseq,   g_tseq);
    cudaGetSymbolAddress((void**)&ff1,    g_ff1);
    cudaGetSymbolAddress((void**)&out3,   g_out3);

    constexpr int SM81 = convSmemBytes(8, 1);   // 92160
    constexpr int SM42 = convSmemBytes(4, 2);   // 55296

    cudaFuncSetAttribute(conv3x3_pipe<8, 1, 1, false>,
                         cudaFuncAttributeMaxDynamicSharedMemorySize, SM81);
    cudaFuncSetAttribute(conv3x3_pipe<8, 1, 0, false>,
                         cudaFuncAttributeMaxDynamicSharedMemorySize, SM81);
    cudaFuncSetAttribute(conv3x3_pipe<8, 1, 0, true>,
                         cudaFuncAttributeMaxDynamicSharedMemorySize, SM81);
    cudaFuncSetAttribute(conv3x3_pipe<4, 2, 1, false>,
                         cudaFuncAttributeMaxDynamicSharedMemorySize, SM42);

    // 1. qk_in
    build_qkin_kernel<<<(BB * HWSZ + 255) / 256, 256>>>(frame, flow_f, flow_b, qkin);

    // 2. qureys = lrelu(conv(qk_in, W_qk))      cin=100 COUT=96
    conv3x3_pipe<8, 1, 1, false><<<dim3(8, 8, BB * 6), 256, SM81>>>(
        qkin, W_qk, b_qk, nullptr, 0, qureys, 100, 96,
        nullptr, nullptr, nullptr, 0, 0);

    // 3. value = conv(frame(96ch), W_v)         cin=96 COUT=96
    conv3x3_pipe<8, 1, 0, false><<<dim3(8, 8, BB * 6), 256, SM81>>>(
        frame, W_v, b_v, nullptr, 0, value, 96, 96,
        nullptr, nullptr, nullptr, 0, 0);

    // 4. val = conv(value as 6 x 32ch, W_vp)    nimg=6 cin=32 COUT=32
    conv3x3_pipe<8, 1, 0, false><<<dim3(8, 8, 6 * 2), 256, SM81>>>(
        value, W_vp, b_vp, nullptr, 0, val, 32, 32,
        nullptr, nullptr, nullptr, 0, 0);

    // 5+6. merged: off = conv(qureys, W_off) [z 0..11] ; aw = conv(qureys, W_aw) [z 12..17]
    conv3x3_pipe<8, 1, 0, false><<<dim3(8, 8, BB * 6 + BB * 3), 256, SM81>>>(
        qureys, W_off, b_off, nullptr, 0, off, 96, 96,
        W_aw, b_aw, aw, 48, BB * 6);

    // 7. deformable attention
    deform_attn_kernel<<<(BB * 4 * HWSZ + 255) / 256, 256>>>(val, off, aw, attn);

    // 8. out1 = conv(attn, W_out)
    conv3x3_pipe<8, 1, 0, false><<<dim3(8, 8, BB * 2), 256, SM81>>>(
        attn, W_out, b_out, nullptr, 0, out1, 32, 32,
        nullptr, nullptr, nullptr, 0, 0);

    // 9. out2 = conv(out1, W_ffd) + frame[:,1]
    conv3x3_pipe<8, 1, 0, true><<<dim3(8, 8, BB * 2), 256, SM81>>>(
        out1, W_ffd, b_ffd, frame + (size_t)32 * HWSZ, (size_t)3 * 32 * HWSZ, out2, 32, 32,
        nullptr, nullptr, nullptr, 0, 0);

    // 10. tseq = concat(out2, srcframe[:,1])
    build_tseq_kernel<<<(BB * 64 * HWSZ + 255) / 256, 256>>>(out2, srcfr, tseq);

    // 11. ff1 = lrelu(conv(tseq, W_ff1, pad=2, dil=2))   cin=64 COUT=32
    conv3x3_pipe<4, 2, 1, false><<<dim3(8, 8, BB * 2), 256, SM42>>>(
        tseq, W_ff1, b_ff1, nullptr, 0, ff1, 64, 32,
        nullptr, nullptr, nullptr, 0, 0);

    // 12. out3 = conv(ff1, W_ff2) + out2
    conv3x3_pipe<8, 1, 0, true><<<dim3(8, 8, BB * 2), 256, SM81>>>(
        ff1, W_ff2, b_ff2, out2, (size_t)32 * HWSZ, out3, 32, 32,
        nullptr, nullptr, nullptr, 0, 0);

    // 13. out = lrelu(conv1x1(out3, W_fu))
    conv1x1_lrelu_kernel<<<(BB * HWSZ + 255) / 256, 256>>>(out3, W_fu, b_fu, (float*)d_out);
}